// round 13
// baseline (speedup 1.0000x reference)
#include <cuda_runtime.h>
#include <cuda_bf16.h>
#include <cstdint>

// ---------------------------------------------------------------------------
// Problem constants
// ---------------------------------------------------------------------------
#define BATCH 4
#define CH    768
#define TLEN  1000
#define HEADS 12
#define HDIM  64
#define WSZ   16
#define NWIN  63
#define NTOK  (BATCH*TLEN)       // 4000
#define MLPC  (4*CH)             // 3072
#define CTOK  TLEN               // tokens per chunk (1 batch)
#define NCHUNK 4

// ---------------------------------------------------------------------------
// Scratch (device globals; allocation-free)
// ---------------------------------------------------------------------------
__device__ __nv_bfloat16  g_snh [NTOK*CH];
__device__ __nv_bfloat16  g_qkvh[NTOK*3*CH];
__device__ __nv_bfloat16  g_atth[NTOK*CH];
__device__ float          g_y0  [NTOK*CH];
__device__ __nv_bfloat16  g_y0h [NTOK*CH];
__device__ __nv_bfloat16  g_mlph[NTOK*MLPC];
__device__ float          g_o   [NTOK*CH];
__device__ float          g_part[4*NTOK*CH];      // [chunk][4][CTOK][CH]
__device__ __nv_bfloat16  g_wqkvT [3*CH*CH];
__device__ __nv_bfloat16  g_wprojT[CH*CH];
__device__ __nv_bfloat16  g_wmlp1T[MLPC*CH];
__device__ __nv_bfloat16  g_wmlp2T[CH*MLPC];

// ---------------------------------------------------------------------------
// Helpers
// ---------------------------------------------------------------------------
__device__ __forceinline__ uint32_t smem_u32(const void* p) {
    uint32_t a;
    asm("{ .reg .u64 t; cvta.to.shared.u64 t, %1; cvt.u32.u64 %0, t; }" : "=r"(a) : "l"(p));
    return a;
}

__device__ __forceinline__ void mma_bf16(float* c, const uint32_t* a, const uint32_t* b) {
    asm volatile(
        "mma.sync.aligned.m16n8k16.row.col.f32.bf16.bf16.f32 "
        "{%0,%1,%2,%3},{%4,%5,%6,%7},{%8,%9},{%0,%1,%2,%3};"
        : "+f"(c[0]), "+f"(c[1]), "+f"(c[2]), "+f"(c[3])
        : "r"(a[0]), "r"(a[1]), "r"(a[2]), "r"(a[3]), "r"(b[0]), "r"(b[1]));
}

__device__ __forceinline__ void cp_async16_sh(uint32_t dst, const void* src, int n) {
    asm volatile("cp.async.cg.shared.global [%0], [%1], 16, %2;"
                 :: "r"(dst), "l"(src), "r"(n));
}

#define LDSM_X4(r0, r1, r2, r3, addr)                                         \
    asm volatile("ldmatrix.sync.aligned.m8n8.x4.shared.b16 {%0,%1,%2,%3}, [%4];" \
                 : "=r"(r0), "=r"(r1), "=r"(r2), "=r"(r3) : "r"(addr))

// ---------------------------------------------------------------------------
// K1: fused spatial mean + LayerNorm.  One block per token; b0 = batch offset.
// ---------------------------------------------------------------------------
__global__ __launch_bounds__(256)
void meanln_kernel(const float* __restrict__ x, const float* __restrict__ gg,
                   const float* __restrict__ bb, __nv_bfloat16* __restrict__ sn,
                   int b0) {
    __shared__ float red[2][8];
    int tokl = blockIdx.x;             // 0..CTOK-1
    int b    = b0 + tokl / TLEN;
    int t    = tokl % TLEN;
    int tid  = threadIdx.x;            // 256

    float sval[3];
    float psum = 0.f, psq = 0.f;
    #pragma unroll
    for (int j = 0; j < 3; j++) {
        int c = tid + j * 256;
        const float4* p = reinterpret_cast<const float4*>(
            x + ((size_t)(b * CH + c) * TLEN + t) * 64);
        float acc = 0.f;
        #pragma unroll
        for (int i = 0; i < 16; i++) {
            float4 v = p[i];
            acc += (v.x + v.y) + (v.z + v.w);
        }
        float s = acc * (1.0f/64.0f);
        sval[j] = s;
        psum += s;
        psq  += s * s;
    }
    #pragma unroll
    for (int m = 16; m; m >>= 1) {
        psum += __shfl_xor_sync(0xffffffffu, psum, m);
        psq  += __shfl_xor_sync(0xffffffffu, psq,  m);
    }
    if ((tid & 31) == 0) { red[0][tid>>5] = psum; red[1][tid>>5] = psq; }
    __syncthreads();
    if (tid < 32) {
        float a  = (tid < 8) ? red[0][tid] : 0.f;
        float b2 = (tid < 8) ? red[1][tid] : 0.f;
        #pragma unroll
        for (int m = 4; m; m >>= 1) {
            a  += __shfl_xor_sync(0xffffffffu, a,  m);
            b2 += __shfl_xor_sync(0xffffffffu, b2, m);
        }
        if (tid == 0) { red[0][0] = a; red[1][0] = b2; }
    }
    __syncthreads();
    float mean = red[0][0] * (1.0f/768.0f);
    float var  = red[1][0] * (1.0f/768.0f) - mean*mean;
    float rstd = rsqrtf(var + 1e-5f);
    __nv_bfloat16* orow = sn + ((size_t)b * TLEN + t) * CH;
    #pragma unroll
    for (int j = 0; j < 3; j++) {
        int c = tid + j * 256;
        orow[c] = __float2bfloat16((sval[j]-mean)*rstd*gg[c] + bb[c]);
    }
}

// ---------------------------------------------------------------------------
// K3: weight convert + transpose.  W fp32 [K][N] -> WT bf16 [N][K]
// ---------------------------------------------------------------------------
__global__ void wconv_kernel(const float* __restrict__ W, __nv_bfloat16* __restrict__ WT,
                             int K, int N) {
    __shared__ float t[64][33];
    int bx = blockIdx.x * 32;   // n base
    int by = blockIdx.y * 64;   // k base
    int tx = threadIdx.x, ty = threadIdx.y;    // 32 x 8
    #pragma unroll
    for (int i = ty; i < 64; i += 8)
        t[i][tx] = W[(size_t)(by + i) * N + bx + tx];
    __syncthreads();
    #pragma unroll
    for (int i = ty; i < 32; i += 8) {
        __nv_bfloat162 h = __floats2bfloat162_rn(t[2*tx][i], t[2*tx+1][i]);
        *reinterpret_cast<__nv_bfloat162*>(WT + (size_t)(bx + i) * K + by + 2*tx) = h;
    }
}

// ---------------------------------------------------------------------------
// GEMM: C = A(MxK,bf16 row-major) @ BT(NxK,bf16 K-major)^T
// bf16 mma.sync m16n8k16, block 128x128x64, 8 warps (2x4), warp tile 64x32.
// 2-stage cp.async, 1 barrier per 64-K slice, ldmatrix.x4 (72-half stride).
// EPI: 1 = bias + exact GELU -> bf16 Ch
//      4 = bias -> bf16 Ch
//      5 = raw partial (no bias) -> fp32 C at split offset (blockIdx.z)
// ---------------------------------------------------------------------------
#define GS_OPER   18432u
#define GS_STAGE  36864u
#define GS_TOTAL  73728

template<int EPI, int SPLIT>
__global__ __launch_bounds__(256, 2)
void gemm_bf16(const __nv_bfloat16* __restrict__ A, const __nv_bfloat16* __restrict__ BT,
               const float* __restrict__ bias,
               float* __restrict__ C, __nv_bfloat16* __restrict__ Ch,
               int M, int N, int K)
{
    extern __shared__ __nv_bfloat16 smem[];
    const uint32_t smemu = smem_u32(smem);

    int tid  = threadIdx.x;
    int lane = tid & 31, warp = tid >> 5;
    int wm = warp >> 2, wn = warp & 3;
    int bm = blockIdx.y * 128, bn = blockIdx.x * 128;
    int g  = lane >> 2, tg = lane & 3;

    const int KTtot = K >> 6;
    const int per   = KTtot / SPLIT;
    const int kz    = (SPLIT > 1) ? blockIdx.z : 0;
    const int kt0   = kz * per;
    const int kt1   = kt0 + per;

    int crow  = tid >> 1;
    int coffh = (tid & 1) * 32;
    int arow = bm + crow; if (arow > M-1) arow = M-1;
    int aok  = (bm + crow < M) ? 16 : 0;
    const __nv_bfloat16* gA = A  + (size_t)arow      * K + coffh;
    const __nv_bfloat16* gB = BT + (size_t)(bn+crow) * K + coffh;
    const uint32_t dstOff = (uint32_t)crow * 144u + (uint32_t)coffh * 2u;

    const uint32_t aFrag = (uint32_t)(wm*64 + (lane & 7) + ((lane >> 3) & 1) * 8) * 144u
                         + (uint32_t)((lane >> 4) * 8) * 2u;
    const uint32_t bFrag = (uint32_t)(wn*32 + (lane & 7) + ((lane >> 4) & 1) * 8) * 144u
                         + (uint32_t)(((lane >> 3) & 1) * 8) * 2u;

    float acc[4][4][4];
    #pragma unroll
    for (int i = 0; i < 4; i++)
        #pragma unroll
        for (int j = 0; j < 4; j++)
            #pragma unroll
            for (int r = 0; r < 4; r++) acc[i][j][r] = 0.f;

    auto prefetch = [&](int c) {
        uint32_t da = smemu + (uint32_t)(c & 1) * GS_STAGE + dstOff;
        uint32_t db = da + GS_OPER;
        const __nv_bfloat16* sa = gA + c * 64;
        const __nv_bfloat16* sb = gB + c * 64;
        #pragma unroll
        for (int j = 0; j < 4; j++) {
            cp_async16_sh(da + j*16u, sa + j*8, aok);
            cp_async16_sh(db + j*16u, sb + j*8, 16);
        }
        asm volatile("cp.async.commit_group;");
    };

    prefetch(kt0);

    for (int kt = kt0; kt < kt1; kt++) {
        asm volatile("cp.async.wait_group 0;");
        __syncthreads();
        if (kt + 1 < kt1) prefetch(kt + 1);

        uint32_t aB = smemu + (uint32_t)(kt & 1) * GS_STAGE + aFrag;
        uint32_t bB = aB - aFrag + GS_OPER + bFrag;
        #pragma unroll
        for (int kk = 0; kk < 4; kk++) {
            uint32_t kby = (uint32_t)kk * 32u;
            uint32_t af[4][4], bf[4][2];
            #pragma unroll
            for (int mi = 0; mi < 4; mi++)
                LDSM_X4(af[mi][0], af[mi][1], af[mi][2], af[mi][3],
                        aB + (uint32_t)mi * (16u*144u) + kby);
            #pragma unroll
            for (int p = 0; p < 2; p++)
                LDSM_X4(bf[2*p][0], bf[2*p][1], bf[2*p+1][0], bf[2*p+1][1],
                        bB + (uint32_t)p * (16u*144u) + kby);
            #pragma unroll
            for (int mi = 0; mi < 4; mi++)
                #pragma unroll
                for (int ni = 0; ni < 4; ni++)
                    mma_bf16(acc[mi][ni], af[mi], bf[ni]);
        }
    }

    // ---- epilogue ----
    float* Cpart = (EPI == 5) ? (C + (size_t)kz * M * N) : C;
    #pragma unroll
    for (int mi = 0; mi < 4; mi++) {
        int r0 = bm + wm*64 + mi*16 + g;
        #pragma unroll
        for (int ni = 0; ni < 4; ni++) {
            int c0 = bn + wn*32 + ni*8 + 2*tg;
            float b0 = 0.f, b1 = 0.f;
            if (EPI != 5) { b0 = bias[c0]; b1 = bias[c0+1]; }
            #pragma unroll
            for (int half = 0; half < 2; half++) {
                int r = r0 + half*8;
                if (r < M) {
                    float v0 = acc[mi][ni][half*2]   + b0;
                    float v1 = acc[mi][ni][half*2+1] + b1;
                    if (EPI == 1) { v0 = v0 * normcdff(v0); v1 = v1 * normcdff(v1); }
                    if (EPI == 5)
                        *reinterpret_cast<float2*>(Cpart + (size_t)r*N + c0) = make_float2(v0, v1);
                    else
                        *reinterpret_cast<__nv_bfloat162*>(Ch + (size_t)r*N + c0) =
                            __floats2bfloat162_rn(v0, v1);
                }
            }
        }
    }
}

// ---------------------------------------------------------------------------
// Split-K reduce kernels (fixed-order sums -> deterministic). Per chunk.
// ---------------------------------------------------------------------------
__global__ void reduce_proj_kernel(const float* __restrict__ part,
                                   const float* __restrict__ bias,
                                   float* __restrict__ y0, __nv_bfloat16* __restrict__ y0h) {
    unsigned i = blockIdx.x * 256u + threadIdx.x;       // over CTOK*CH/4
    if (i >= (unsigned)(CTOK*CH/4)) return;
    const float4 p0 = reinterpret_cast<const float4*>(part)[i];
    const float4 p1 = reinterpret_cast<const float4*>(part + (size_t)CTOK*CH)[i];
    const float4 bv = reinterpret_cast<const float4*>(bias)[i % (CH/4)];
    float4 v;
    v.x = p0.x + p1.x + bv.x;
    v.y = p0.y + p1.y + bv.y;
    v.z = p0.z + p1.z + bv.z;
    v.w = p0.w + p1.w + bv.w;
    reinterpret_cast<float4*>(y0)[i] = v;
    reinterpret_cast<__nv_bfloat162*>(y0h)[2*i]   = __floats2bfloat162_rn(v.x, v.y);
    reinterpret_cast<__nv_bfloat162*>(y0h)[2*i+1] = __floats2bfloat162_rn(v.z, v.w);
}

__global__ void reduce_mlp2_kernel(const float* __restrict__ part,
                                   const float* __restrict__ bias,
                                   const float* __restrict__ y0,
                                   float* __restrict__ o) {
    unsigned i = blockIdx.x * 256u + threadIdx.x;       // over CTOK*CH/4
    if (i >= (unsigned)(CTOK*CH/4)) return;
    const size_t str = (size_t)CTOK*CH;
    const float4 p0 = reinterpret_cast<const float4*>(part)[i];
    const float4 p1 = reinterpret_cast<const float4*>(part + str)[i];
    const float4 p2 = reinterpret_cast<const float4*>(part + 2*str)[i];
    const float4 p3 = reinterpret_cast<const float4*>(part + 3*str)[i];
    const float4 bv = reinterpret_cast<const float4*>(bias)[i % (CH/4)];
    const float4 rv = reinterpret_cast<const float4*>(y0)[i];
    float4 v;
    v.x = ((p0.x + p1.x) + (p2.x + p3.x)) + bv.x + rv.x;
    v.y = ((p0.y + p1.y) + (p2.y + p3.y)) + bv.y + rv.y;
    v.z = ((p0.z + p1.z) + (p2.z + p3.z)) + bv.z + rv.z;
    v.w = ((p0.w + p1.w) + (p2.w + p3.w)) + bv.w + rv.w;
    reinterpret_cast<float4*>(o)[i] = v;
}

// ---------------------------------------------------------------------------
// K4: windowed cosine attention (bf16 in, bf16 out). Pointers pre-offset
// to chunk (1 batch).
// ---------------------------------------------------------------------------
__global__ void attn_kernel(const __nv_bfloat16* __restrict__ qkv,
                            const float* __restrict__ tau,
                            __nv_bfloat16* __restrict__ att) {
    __shared__ float qs[16][68], ks[16][68], vs[16][68];
    __shared__ float rq[16], rk[16];
    __shared__ float at[16][17];
    __shared__ float tauv;

    int n = blockIdx.x, hh = blockIdx.y;
    int tid = threadIdx.x;                  // 256

    {
        int rr  = tid >> 4;
        int c4 = (tid & 15) << 2;
        int t  = n*WSZ + rr;
        float4 q4 = make_float4(0.f,0.f,0.f,0.f), k4 = q4, v4 = q4;
        if (t < TLEN) {
            size_t bb = (size_t)t * (3*CH) + hh*HDIM + c4;
            uint2 qu = *reinterpret_cast<const uint2*>(qkv + bb);
            uint2 ku = *reinterpret_cast<const uint2*>(qkv + bb + CH);
            uint2 vu = *reinterpret_cast<const uint2*>(qkv + bb + 2*CH);
            float2 a0 = __bfloat1622float2(*reinterpret_cast<__nv_bfloat162*>(&qu.x));
            float2 a1 = __bfloat1622float2(*reinterpret_cast<__nv_bfloat162*>(&qu.y));
            q4 = make_float4(a0.x, a0.y, a1.x, a1.y);
            a0 = __bfloat1622float2(*reinterpret_cast<__nv_bfloat162*>(&ku.x));
            a1 = __bfloat1622float2(*reinterpret_cast<__nv_bfloat162*>(&ku.y));
            k4 = make_float4(a0.x, a0.y, a1.x, a1.y);
            a0 = __bfloat1622float2(*reinterpret_cast<__nv_bfloat162*>(&vu.x));
            a1 = __bfloat1622float2(*reinterpret_cast<__nv_bfloat162*>(&vu.y));
            v4 = make_float4(a0.x, a0.y, a1.x, a1.y);
        }
        *reinterpret_cast<float4*>(&qs[rr][c4]) = q4;
        *reinterpret_cast<float4*>(&ks[rr][c4]) = k4;
        *reinterpret_cast<float4*>(&vs[rr][c4]) = v4;
        if (tid == 0) tauv = tau[hh] + 1e-6f;
    }
    __syncthreads();

    if (tid < 32) {
        const float* p = (tid < 16) ? &qs[tid][0] : &ks[tid-16][0];
        float ssum = 0.f;
        #pragma unroll
        for (int i = 0; i < 64; i++) ssum += p[i]*p[i];
        float inv = 1.0f / fmaxf(sqrtf(ssum), 1e-12f);
        if (tid < 16) rq[tid] = inv; else rk[tid-16] = inv;
    }
    __syncthreads();

    int w  = tid >> 4;
    int s2 = tid & 15;
    float dot = 0.f;
    #pragma unroll
    for (int i = 0; i < 64; i++) dot += qs[w][i] * ks[s2][i];
    float logit = dot * rq[w] * rk[s2] / tauv;

    float mx = logit;
    #pragma unroll
    for (int m = 8; m; m >>= 1) mx = fmaxf(mx, __shfl_xor_sync(0xffffffffu, mx, m));
    float e = expf(logit - mx);
    float ssum = e;
    #pragma unroll
    for (int m = 8; m; m >>= 1) ssum += __shfl_xor_sync(0xffffffffu, ssum, m);
    at[w][s2] = e / ssum;
    __syncthreads();

    int c0 = (tid & 15) << 2;
    float o0=0.f, o1=0.f, o2=0.f, o3=0.f;
    #pragma unroll
    for (int ss = 0; ss < 16; ss++) {
        float a = at[w][ss];
        o0 += a * vs[ss][c0+0];
        o1 += a * vs[ss][c0+1];
        o2 += a * vs[ss][c0+2];
        o3 += a * vs[ss][c0+3];
    }
    int t = n*WSZ + w;
    if (t < TLEN) {
        __nv_bfloat16* dst = att + (size_t)t*CH + hh*HDIM + c0;
        *reinterpret_cast<__nv_bfloat162*>(dst)     = __floats2bfloat162_rn(o0, o1);
        *reinterpret_cast<__nv_bfloat162*>(dst + 2) = __floats2bfloat162_rn(o2, o3);
    }
}

// ---------------------------------------------------------------------------
// K8: y = x + o*0.5 broadcast. Pointers pre-offset to chunk (1 batch).
// ---------------------------------------------------------------------------
__global__ void final_kernel(const float* __restrict__ x, const float* __restrict__ o,
                             float* __restrict__ y) {
    unsigned i4 = blockIdx.x * 256u + threadIdx.x;    // over CH*TLEN*16 float4
    if (i4 >= (unsigned)(CH*TLEN*16)) return;
    unsigned row = i4 >> 4;              // (c, t)
    unsigned t  = row % TLEN;
    unsigned c  = row / TLEN;
    float val = __ldg(o + (size_t)t*CH + c) * 0.5f;
    float4 xv = reinterpret_cast<const float4*>(x)[i4];
    xv.x += val; xv.y += val; xv.z += val; xv.w += val;
    reinterpret_cast<float4*>(y)[i4] = xv;
}

// ---------------------------------------------------------------------------
// Launch: four 1-batch pipelines interleaved on TWO worker streams
// (+1 wconv stream) — same stream count as the passing R11 footprint.
// ---------------------------------------------------------------------------
extern "C" void kernel_launch(void* const* d_in, const int* in_sizes, int n_in,
                              void* d_out, int out_size) {
    const float* x      = (const float*)d_in[0];
    const float* ln_g   = (const float*)d_in[1];
    const float* ln_b   = (const float*)d_in[2];
    const float* tau    = (const float*)d_in[3];
    const float* w_qkv  = (const float*)d_in[4];
    const float* b_qkv  = (const float*)d_in[5];
    const float* w_proj = (const float*)d_in[6];
    const float* b_proj = (const float*)d_in[7];
    const float* w_mlp1 = (const float*)d_in[8];
    const float* b_mlp1 = (const float*)d_in[9];
    const float* w_mlp2 = (const float*)d_in[10];
    const float* b_mlp2 = (const float*)d_in[11];
    float* y = (float*)d_out;

    float *y0, *o, *part;
    __nv_bfloat16 *snh, *qkvh, *atth, *y0h, *mlph, *wqkvT, *wprojT, *wmlp1T, *wmlp2T;
    cudaGetSymbolAddress((void**)&snh,    g_snh);
    cudaGetSymbolAddress((void**)&qkvh,   g_qkvh);
    cudaGetSymbolAddress((void**)&atth,   g_atth);
    cudaGetSymbolAddress((void**)&y0,     g_y0);
    cudaGetSymbolAddress((void**)&y0h,    g_y0h);
    cudaGetSymbolAddress((void**)&mlph,   g_mlph);
    cudaGetSymbolAddress((void**)&o,      g_o);
    cudaGetSymbolAddress((void**)&part,   g_part);
    cudaGetSymbolAddress((void**)&wqkvT,  g_wqkvT);
    cudaGetSymbolAddress((void**)&wprojT, g_wprojT);
    cudaGetSymbolAddress((void**)&wmlp1T, g_wmlp1T);
    cudaGetSymbolAddress((void**)&wmlp2T, g_wmlp2T);

    cudaFuncSetAttribute(gemm_bf16<4,1>, cudaFuncAttributeMaxDynamicSharedMemorySize, GS_TOTAL);
    cudaFuncSetAttribute(gemm_bf16<1,1>, cudaFuncAttributeMaxDynamicSharedMemorySize, GS_TOTAL);
    cudaFuncSetAttribute(gemm_bf16<5,2>, cudaFuncAttributeMaxDynamicSharedMemorySize, GS_TOTAL);
    cudaFuncSetAttribute(gemm_bf16<5,4>, cudaFuncAttributeMaxDynamicSharedMemorySize, GS_TOTAL);

    static cudaStream_t sA = nullptr, sB = nullptr, sW = nullptr;
    static cudaEvent_t  e0 = nullptr, eW = nullptr, eA = nullptr, eB = nullptr;
    if (!sA) {
        cudaStreamCreateWithFlags(&sA, cudaStreamNonBlocking);
        cudaStreamCreateWithFlags(&sB, cudaStreamNonBlocking);
        cudaStreamCreateWithFlags(&sW, cudaStreamNonBlocking);
        cudaEventCreateWithFlags(&e0, cudaEventDisableTiming);
        cudaEventCreateWithFlags(&eW, cudaEventDisableTiming);
        cudaEventCreateWithFlags(&eA, cudaEventDisableTiming);
        cudaEventCreateWithFlags(&eB, cudaEventDisableTiming);
    }

    // fork
    cudaEventRecord(e0, 0);
    cudaStreamWaitEvent(sA, e0, 0);
    cudaStreamWaitEvent(sB, e0, 0);
    cudaStreamWaitEvent(sW, e0, 0);

    // weight conversions on sW
    wconv_kernel<<<dim3(3*CH/32, CH/64),  dim3(32,8), 0, sW>>>(w_qkv,  wqkvT,  CH,   3*CH);
    wconv_kernel<<<dim3(CH/32,   CH/64),  dim3(32,8), 0, sW>>>(w_proj, wprojT, CH,   CH);
    wconv_kernel<<<dim3(MLPC/32, CH/64),  dim3(32,8), 0, sW>>>(w_mlp1, wmlp1T, CH,   MLPC);
    wconv_kernel<<<dim3(CH/32,   MLPC/64),dim3(32,8), 0, sW>>>(w_mlp2, wmlp2T, MLPC, CH);
    cudaEventRecord(eW, sW);

    // meanln for ALL chunks first (on their streams), so both workers can
    // start GEMMs as soon as weights are ready.
    cudaStream_t cs[2] = {sA, sB};
    for (int ck = 0; ck < NCHUNK; ck++) {
        cudaStream_t st = cs[ck & 1];
        meanln_kernel<<<CTOK, 256, 0, st>>>(x, ln_g, ln_b, snh, ck);
    }
    cudaStreamWaitEvent(sA, eW, 0);
    cudaStreamWaitEvent(sB, eW, 0);

    for (int ck = 0; ck < NCHUNK; ck++) {
        cudaStream_t st = cs[ck & 1];
        const size_t to  = (size_t)ck * CTOK;          // token offset
        __nv_bfloat16* snh_c  = snh  + to * CH;
        __nv_bfloat16* qkv_c  = qkvh + to * 3*CH;
        __nv_bfloat16* att_c  = atth + to * CH;
        float*         y0_c   = y0   + to * CH;
        __nv_bfloat16* y0h_c  = y0h  + to * CH;
        __nv_bfloat16* mlp_c  = mlph + to * MLPC;
        float*         o_c    = o    + to * CH;
        float*         part_c = part + (size_t)ck * 4 * CTOK * CH;
        const float*   x_c    = x + (size_t)ck * CH * TLEN * 64;
        float*         y_c    = y + (size_t)ck * CH * TLEN * 64;

        // qkv: 1000 x 2304
        gemm_bf16<4,1><<<dim3(3*CH/128, 8), 256, GS_TOTAL, st>>>(
            snh_c, wqkvT, b_qkv, nullptr, qkv_c, CTOK, 3*CH, CH);
        attn_kernel<<<dim3(NWIN, HEADS), 256, 0, st>>>(qkv_c, tau, att_c);

        // proj: 1000 x 768, split-K 2
        gemm_bf16<5,2><<<dim3(CH/128, 8, 2), 256, GS_TOTAL, st>>>(
            att_c, wprojT, nullptr, part_c, nullptr, CTOK, CH, CH);
        reduce_proj_kernel<<<(CTOK*CH/4 + 255)/256, 256, 0, st>>>(part_c, b_proj, y0_c, y0h_c);

        // mlp1 + gelu: 1000 x 3072
        gemm_bf16<1,1><<<dim3(MLPC/128, 8), 256, GS_TOTAL, st>>>(
            y0h_c, wmlp1T, b_mlp1, nullptr, mlp_c, CTOK, MLPC, CH);
        // mlp2: 1000 x 768, split-K 4
        gemm_bf16<5,4><<<dim3(CH/128, 8, 4), 256, GS_TOTAL, st>>>(
            mlp_c, wmlp2T, nullptr, part_c, nullptr, CTOK, CH, MLPC);
        reduce_mlp2_kernel<<<(CTOK*CH/4 + 255)/256, 256, 0, st>>>(part_c, b_mlp2, y0_c, o_c);

        final_kernel<<<(CH*TLEN*16 + 255)/256, 256, 0, st>>>(x_c, o_c, y_c);
    }

    // join
    cudaEventRecord(eA, sA);
    cudaEventRecord(eB, sB);
    cudaStreamWaitEvent(0, eA, 0);
    cudaStreamWaitEvent(0, eB, 0);
}

// round 14
// speedup vs baseline: 1.0264x; 1.0264x over previous
#include <cuda_runtime.h>
#include <cuda_bf16.h>
#include <cstdint>

// ---------------------------------------------------------------------------
// Problem constants
// ---------------------------------------------------------------------------
#define BATCH 4
#define CH    768
#define TLEN  1000
#define HEADS 12
#define HDIM  64
#define WSZ   16
#define NWIN  63
#define NTOK  (BATCH*TLEN)       // 4000
#define MLPC  (4*CH)             // 3072
#define CTOK  2000               // tokens per chunk (2 batches)

// ---------------------------------------------------------------------------
// Scratch (device globals; allocation-free)
// ---------------------------------------------------------------------------
__device__ __nv_bfloat16  g_snh [NTOK*CH];
__device__ __nv_bfloat16  g_qkvh[NTOK*3*CH];
__device__ __nv_bfloat16  g_atth[NTOK*CH];
__device__ float          g_y0  [NTOK*CH];
__device__ __nv_bfloat16  g_y0h [NTOK*CH];
__device__ __nv_bfloat16  g_mlph[NTOK*MLPC];
__device__ float          g_part[4*NTOK*CH];      // [chunk][4][CTOK][CH]
__device__ __nv_bfloat16  g_wqkvT [3*CH*CH];
__device__ __nv_bfloat16  g_wprojT[CH*CH];
__device__ __nv_bfloat16  g_wmlp1T[MLPC*CH];
__device__ __nv_bfloat16  g_wmlp2T[CH*MLPC];

// ---------------------------------------------------------------------------
// Helpers
// ---------------------------------------------------------------------------
__device__ __forceinline__ uint32_t smem_u32(const void* p) {
    uint32_t a;
    asm("{ .reg .u64 t; cvta.to.shared.u64 t, %1; cvt.u32.u64 %0, t; }" : "=r"(a) : "l"(p));
    return a;
}

__device__ __forceinline__ void mma_bf16(float* c, const uint32_t* a, const uint32_t* b) {
    asm volatile(
        "mma.sync.aligned.m16n8k16.row.col.f32.bf16.bf16.f32 "
        "{%0,%1,%2,%3},{%4,%5,%6,%7},{%8,%9},{%0,%1,%2,%3};"
        : "+f"(c[0]), "+f"(c[1]), "+f"(c[2]), "+f"(c[3])
        : "r"(a[0]), "r"(a[1]), "r"(a[2]), "r"(a[3]), "r"(b[0]), "r"(b[1]));
}

__device__ __forceinline__ void cp_async16_sh(uint32_t dst, const void* src, int n) {
    asm volatile("cp.async.cg.shared.global [%0], [%1], 16, %2;"
                 :: "r"(dst), "l"(src), "r"(n));
}

#define LDSM_X4(r0, r1, r2, r3, addr)                                         \
    asm volatile("ldmatrix.sync.aligned.m8n8.x4.shared.b16 {%0,%1,%2,%3}, [%4];" \
                 : "=r"(r0), "=r"(r1), "=r"(r2), "=r"(r3) : "r"(addr))

// ---------------------------------------------------------------------------
// K1: fused spatial mean + LayerNorm.  One block per token; b0 = batch offset.
// ---------------------------------------------------------------------------
__global__ __launch_bounds__(256)
void meanln_kernel(const float* __restrict__ x, const float* __restrict__ gg,
                   const float* __restrict__ bb, __nv_bfloat16* __restrict__ sn,
                   int b0) {
    __shared__ float red[2][8];
    int tokl = blockIdx.x;             // 0..CTOK-1
    int b    = b0 + tokl / TLEN;
    int t    = tokl % TLEN;
    int tid  = threadIdx.x;            // 256

    float sval[3];
    float psum = 0.f, psq = 0.f;
    #pragma unroll
    for (int j = 0; j < 3; j++) {
        int c = tid + j * 256;
        const float4* p = reinterpret_cast<const float4*>(
            x + ((size_t)(b * CH + c) * TLEN + t) * 64);
        float acc = 0.f;
        #pragma unroll
        for (int i = 0; i < 16; i++) {
            float4 v = p[i];
            acc += (v.x + v.y) + (v.z + v.w);
        }
        float s = acc * (1.0f/64.0f);
        sval[j] = s;
        psum += s;
        psq  += s * s;
    }
    #pragma unroll
    for (int m = 16; m; m >>= 1) {
        psum += __shfl_xor_sync(0xffffffffu, psum, m);
        psq  += __shfl_xor_sync(0xffffffffu, psq,  m);
    }
    if ((tid & 31) == 0) { red[0][tid>>5] = psum; red[1][tid>>5] = psq; }
    __syncthreads();
    if (tid < 32) {
        float a  = (tid < 8) ? red[0][tid] : 0.f;
        float b2 = (tid < 8) ? red[1][tid] : 0.f;
        #pragma unroll
        for (int m = 4; m; m >>= 1) {
            a  += __shfl_xor_sync(0xffffffffu, a,  m);
            b2 += __shfl_xor_sync(0xffffffffu, b2, m);
        }
        if (tid == 0) { red[0][0] = a; red[1][0] = b2; }
    }
    __syncthreads();
    float mean = red[0][0] * (1.0f/768.0f);
    float var  = red[1][0] * (1.0f/768.0f) - mean*mean;
    float rstd = rsqrtf(var + 1e-5f);
    __nv_bfloat16* orow = sn + ((size_t)b * TLEN + t) * CH;
    #pragma unroll
    for (int j = 0; j < 3; j++) {
        int c = tid + j * 256;
        orow[c] = __float2bfloat16((sval[j]-mean)*rstd*gg[c] + bb[c]);
    }
}

// ---------------------------------------------------------------------------
// K3: weight convert + transpose.  W fp32 [K][N] -> WT bf16 [N][K]
// ---------------------------------------------------------------------------
__global__ void wconv_kernel(const float* __restrict__ W, __nv_bfloat16* __restrict__ WT,
                             int K, int N) {
    __shared__ float t[64][33];
    int bx = blockIdx.x * 32;   // n base
    int by = blockIdx.y * 64;   // k base
    int tx = threadIdx.x, ty = threadIdx.y;    // 32 x 8
    #pragma unroll
    for (int i = ty; i < 64; i += 8)
        t[i][tx] = W[(size_t)(by + i) * N + bx + tx];
    __syncthreads();
    #pragma unroll
    for (int i = ty; i < 32; i += 8) {
        __nv_bfloat162 h = __floats2bfloat162_rn(t[2*tx][i], t[2*tx+1][i]);
        *reinterpret_cast<__nv_bfloat162*>(WT + (size_t)(bx + i) * K + by + 2*tx) = h;
    }
}

// ---------------------------------------------------------------------------
// GEMM: C = A(MxK,bf16 row-major) @ BT(NxK,bf16 K-major)^T
// bf16 mma.sync m16n8k16, block 128x128x64, 8 warps (2x4), warp tile 64x32.
// 2-stage cp.async, 1 barrier per 64-K slice, ldmatrix.x4 (72-half stride).
// EPI: 1 = bias + exact GELU -> bf16 Ch
//      4 = bias -> bf16 Ch
//      5 = raw partial (no bias) -> fp32 C at split offset (blockIdx.z)
// ---------------------------------------------------------------------------
#define GS_OPER   18432u
#define GS_STAGE  36864u
#define GS_TOTAL  73728

template<int EPI, int SPLIT>
__global__ __launch_bounds__(256, 2)
void gemm_bf16(const __nv_bfloat16* __restrict__ A, const __nv_bfloat16* __restrict__ BT,
               const float* __restrict__ bias,
               float* __restrict__ C, __nv_bfloat16* __restrict__ Ch,
               int M, int N, int K)
{
    extern __shared__ __nv_bfloat16 smem[];
    const uint32_t smemu = smem_u32(smem);

    int tid  = threadIdx.x;
    int lane = tid & 31, warp = tid >> 5;
    int wm = warp >> 2, wn = warp & 3;
    int bm = blockIdx.y * 128, bn = blockIdx.x * 128;
    int g  = lane >> 2, tg = lane & 3;

    const int KTtot = K >> 6;
    const int per   = KTtot / SPLIT;
    const int kz    = (SPLIT > 1) ? blockIdx.z : 0;
    const int kt0   = kz * per;
    const int kt1   = kt0 + per;

    int crow  = tid >> 1;
    int coffh = (tid & 1) * 32;
    int arow = bm + crow; if (arow > M-1) arow = M-1;
    int aok  = (bm + crow < M) ? 16 : 0;
    const __nv_bfloat16* gA = A  + (size_t)arow      * K + coffh;
    const __nv_bfloat16* gB = BT + (size_t)(bn+crow) * K + coffh;
    const uint32_t dstOff = (uint32_t)crow * 144u + (uint32_t)coffh * 2u;

    const uint32_t aFrag = (uint32_t)(wm*64 + (lane & 7) + ((lane >> 3) & 1) * 8) * 144u
                         + (uint32_t)((lane >> 4) * 8) * 2u;
    const uint32_t bFrag = (uint32_t)(wn*32 + (lane & 7) + ((lane >> 4) & 1) * 8) * 144u
                         + (uint32_t)(((lane >> 3) & 1) * 8) * 2u;

    float acc[4][4][4];
    #pragma unroll
    for (int i = 0; i < 4; i++)
        #pragma unroll
        for (int j = 0; j < 4; j++)
            #pragma unroll
            for (int r = 0; r < 4; r++) acc[i][j][r] = 0.f;

    auto prefetch = [&](int c) {
        uint32_t da = smemu + (uint32_t)(c & 1) * GS_STAGE + dstOff;
        uint32_t db = da + GS_OPER;
        const __nv_bfloat16* sa = gA + c * 64;
        const __nv_bfloat16* sb = gB + c * 64;
        #pragma unroll
        for (int j = 0; j < 4; j++) {
            cp_async16_sh(da + j*16u, sa + j*8, aok);
            cp_async16_sh(db + j*16u, sb + j*8, 16);
        }
        asm volatile("cp.async.commit_group;");
    };

    prefetch(kt0);

    for (int kt = kt0; kt < kt1; kt++) {
        asm volatile("cp.async.wait_group 0;");
        __syncthreads();
        if (kt + 1 < kt1) prefetch(kt + 1);

        uint32_t aB = smemu + (uint32_t)(kt & 1) * GS_STAGE + aFrag;
        uint32_t bB = aB - aFrag + GS_OPER + bFrag;
        #pragma unroll
        for (int kk = 0; kk < 4; kk++) {
            uint32_t kby = (uint32_t)kk * 32u;
            uint32_t af[4][4], bf[4][2];
            #pragma unroll
            for (int mi = 0; mi < 4; mi++)
                LDSM_X4(af[mi][0], af[mi][1], af[mi][2], af[mi][3],
                        aB + (uint32_t)mi * (16u*144u) + kby);
            #pragma unroll
            for (int p = 0; p < 2; p++)
                LDSM_X4(bf[2*p][0], bf[2*p][1], bf[2*p+1][0], bf[2*p+1][1],
                        bB + (uint32_t)p * (16u*144u) + kby);
            #pragma unroll
            for (int mi = 0; mi < 4; mi++)
                #pragma unroll
                for (int ni = 0; ni < 4; ni++)
                    mma_bf16(acc[mi][ni], af[mi], bf[ni]);
        }
    }

    // ---- epilogue ----
    float* Cpart = (EPI == 5) ? (C + (size_t)kz * M * N) : C;
    #pragma unroll
    for (int mi = 0; mi < 4; mi++) {
        int r0 = bm + wm*64 + mi*16 + g;
        #pragma unroll
        for (int ni = 0; ni < 4; ni++) {
            int c0 = bn + wn*32 + ni*8 + 2*tg;
            float b0 = 0.f, b1 = 0.f;
            if (EPI != 5) { b0 = bias[c0]; b1 = bias[c0+1]; }
            #pragma unroll
            for (int half = 0; half < 2; half++) {
                int r = r0 + half*8;
                if (r < M) {
                    float v0 = acc[mi][ni][half*2]   + b0;
                    float v1 = acc[mi][ni][half*2+1] + b1;
                    if (EPI == 1) { v0 = v0 * normcdff(v0); v1 = v1 * normcdff(v1); }
                    if (EPI == 5)
                        *reinterpret_cast<float2*>(Cpart + (size_t)r*N + c0) = make_float2(v0, v1);
                    else
                        *reinterpret_cast<__nv_bfloat162*>(Ch + (size_t)r*N + c0) =
                            __floats2bfloat162_rn(v0, v1);
                }
            }
        }
    }
}

// ---------------------------------------------------------------------------
// Split-K reduce for proj (fixed-order sums -> deterministic). Per chunk.
// ---------------------------------------------------------------------------
__global__ void reduce_proj_kernel(const float* __restrict__ part,
                                   const float* __restrict__ bias,
                                   float* __restrict__ y0, __nv_bfloat16* __restrict__ y0h) {
    unsigned i = blockIdx.x * 256u + threadIdx.x;       // over CTOK*CH/4
    if (i >= (unsigned)(CTOK*CH/4)) return;
    const float4 p0 = reinterpret_cast<const float4*>(part)[i];
    const float4 p1 = reinterpret_cast<const float4*>(part + (size_t)CTOK*CH)[i];
    const float4 bv = reinterpret_cast<const float4*>(bias)[i % (CH/4)];
    float4 v;
    v.x = p0.x + p1.x + bv.x;
    v.y = p0.y + p1.y + bv.y;
    v.z = p0.z + p1.z + bv.z;
    v.w = p0.w + p1.w + bv.w;
    reinterpret_cast<float4*>(y0)[i] = v;
    reinterpret_cast<__nv_bfloat162*>(y0h)[2*i]   = __floats2bfloat162_rn(v.x, v.y);
    reinterpret_cast<__nv_bfloat162*>(y0h)[2*i+1] = __floats2bfloat162_rn(v.z, v.w);
}

// ---------------------------------------------------------------------------
// K4: windowed cosine attention (bf16 in, bf16 out). Pointers pre-offset
// to chunk; blockIdx.z = local batch.
// ---------------------------------------------------------------------------
__global__ void attn_kernel(const __nv_bfloat16* __restrict__ qkv,
                            const float* __restrict__ tau,
                            __nv_bfloat16* __restrict__ att) {
    __shared__ float qs[16][68], ks[16][68], vs[16][68];
    __shared__ float rq[16], rk[16];
    __shared__ float at[16][17];
    __shared__ float tauv;

    int n = blockIdx.x, hh = blockIdx.y, b = blockIdx.z;
    int tid = threadIdx.x;                  // 256

    {
        int rr  = tid >> 4;
        int c4 = (tid & 15) << 2;
        int t  = n*WSZ + rr;
        float4 q4 = make_float4(0.f,0.f,0.f,0.f), k4 = q4, v4 = q4;
        if (t < TLEN) {
            size_t bb = (size_t)(b*TLEN + t) * (3*CH) + hh*HDIM + c4;
            uint2 qu = *reinterpret_cast<const uint2*>(qkv + bb);
            uint2 ku = *reinterpret_cast<const uint2*>(qkv + bb + CH);
            uint2 vu = *reinterpret_cast<const uint2*>(qkv + bb + 2*CH);
            float2 a0 = __bfloat1622float2(*reinterpret_cast<__nv_bfloat162*>(&qu.x));
            float2 a1 = __bfloat1622float2(*reinterpret_cast<__nv_bfloat162*>(&qu.y));
            q4 = make_float4(a0.x, a0.y, a1.x, a1.y);
            a0 = __bfloat1622float2(*reinterpret_cast<__nv_bfloat162*>(&ku.x));
            a1 = __bfloat1622float2(*reinterpret_cast<__nv_bfloat162*>(&ku.y));
            k4 = make_float4(a0.x, a0.y, a1.x, a1.y);
            a0 = __bfloat1622float2(*reinterpret_cast<__nv_bfloat162*>(&vu.x));
            a1 = __bfloat1622float2(*reinterpret_cast<__nv_bfloat162*>(&vu.y));
            v4 = make_float4(a0.x, a0.y, a1.x, a1.y);
        }
        *reinterpret_cast<float4*>(&qs[rr][c4]) = q4;
        *reinterpret_cast<float4*>(&ks[rr][c4]) = k4;
        *reinterpret_cast<float4*>(&vs[rr][c4]) = v4;
        if (tid == 0) tauv = tau[hh] + 1e-6f;
    }
    __syncthreads();

    if (tid < 32) {
        const float* p = (tid < 16) ? &qs[tid][0] : &ks[tid-16][0];
        float ssum = 0.f;
        #pragma unroll
        for (int i = 0; i < 64; i++) ssum += p[i]*p[i];
        float inv = 1.0f / fmaxf(sqrtf(ssum), 1e-12f);
        if (tid < 16) rq[tid] = inv; else rk[tid-16] = inv;
    }
    __syncthreads();

    int w  = tid >> 4;
    int s2 = tid & 15;
    float dot = 0.f;
    #pragma unroll
    for (int i = 0; i < 64; i++) dot += qs[w][i] * ks[s2][i];
    float logit = dot * rq[w] * rk[s2] / tauv;

    float mx = logit;
    #pragma unroll
    for (int m = 8; m; m >>= 1) mx = fmaxf(mx, __shfl_xor_sync(0xffffffffu, mx, m));
    float e = expf(logit - mx);
    float ssum = e;
    #pragma unroll
    for (int m = 8; m; m >>= 1) ssum += __shfl_xor_sync(0xffffffffu, ssum, m);
    at[w][s2] = e / ssum;
    __syncthreads();

    int c0 = (tid & 15) << 2;
    float o0=0.f, o1=0.f, o2=0.f, o3=0.f;
    #pragma unroll
    for (int ss = 0; ss < 16; ss++) {
        float a = at[w][ss];
        o0 += a * vs[ss][c0+0];
        o1 += a * vs[ss][c0+1];
        o2 += a * vs[ss][c0+2];
        o3 += a * vs[ss][c0+3];
    }
    int t = n*WSZ + w;
    if (t < TLEN) {
        __nv_bfloat16* dst = att + (size_t)(b*TLEN + t)*CH + hh*HDIM + c0;
        *reinterpret_cast<__nv_bfloat162*>(dst)     = __floats2bfloat162_rn(o0, o1);
        *reinterpret_cast<__nv_bfloat162*>(dst + 2) = __floats2bfloat162_rn(o2, o3);
    }
}

// ---------------------------------------------------------------------------
// K8: fused mlp2-reduce + residual + broadcast:
// y = x + (sum4(part) + b_mlp2 + y0) * 0.5, per chunk (2 batches).
// Row-group broadcast loads are L1-served (16 threads share each scalar).
// Sum order identical to the former reduce_mlp2_kernel.
// ---------------------------------------------------------------------------
__global__ void final_fused_kernel(const float* __restrict__ x,
                                   const float* __restrict__ part,
                                   const float* __restrict__ bias,
                                   const float* __restrict__ y0,
                                   float* __restrict__ y) {
    unsigned i4 = blockIdx.x * 256u + threadIdx.x;    // over 2*CH*TLEN*16 float4
    if (i4 >= (unsigned)(2*CH*TLEN*16)) return;
    unsigned row = i4 >> 4;              // (b_local, c, t)
    unsigned t  = row % TLEN;
    unsigned bc = row / TLEN;
    unsigned c  = bc % CH;
    unsigned b  = bc / CH;               // 0..1
    const size_t idx = ((size_t)b*TLEN + t)*CH + c;
    const size_t str = (size_t)CTOK*CH;
    float p = (__ldg(part + idx)       + __ldg(part + str   + idx))
            + (__ldg(part + 2*str+idx) + __ldg(part + 3*str + idx));
    float val = ((p + __ldg(bias + c)) + __ldg(y0 + idx)) * 0.5f;
    float4 xv = reinterpret_cast<const float4*>(x)[i4];
    xv.x += val; xv.y += val; xv.z += val; xv.w += val;
    reinterpret_cast<float4*>(y)[i4] = xv;
}

// ---------------------------------------------------------------------------
// Launch: two independent token-chunk pipelines on two streams (R11 topology).
// ---------------------------------------------------------------------------
extern "C" void kernel_launch(void* const* d_in, const int* in_sizes, int n_in,
                              void* d_out, int out_size) {
    const float* x      = (const float*)d_in[0];
    const float* ln_g   = (const float*)d_in[1];
    const float* ln_b   = (const float*)d_in[2];
    const float* tau    = (const float*)d_in[3];
    const float* w_qkv  = (const float*)d_in[4];
    const float* b_qkv  = (const float*)d_in[5];
    const float* w_proj = (const float*)d_in[6];
    const float* b_proj = (const float*)d_in[7];
    const float* w_mlp1 = (const float*)d_in[8];
    const float* b_mlp1 = (const float*)d_in[9];
    const float* w_mlp2 = (const float*)d_in[10];
    const float* b_mlp2 = (const float*)d_in[11];
    float* y = (float*)d_out;

    float *y0, *part;
    __nv_bfloat16 *snh, *qkvh, *atth, *y0h, *mlph, *wqkvT, *wprojT, *wmlp1T, *wmlp2T;
    cudaGetSymbolAddress((void**)&snh,    g_snh);
    cudaGetSymbolAddress((void**)&qkvh,   g_qkvh);
    cudaGetSymbolAddress((void**)&atth,   g_atth);
    cudaGetSymbolAddress((void**)&y0,     g_y0);
    cudaGetSymbolAddress((void**)&y0h,    g_y0h);
    cudaGetSymbolAddress((void**)&mlph,   g_mlph);
    cudaGetSymbolAddress((void**)&part,   g_part);
    cudaGetSymbolAddress((void**)&wqkvT,  g_wqkvT);
    cudaGetSymbolAddress((void**)&wprojT, g_wprojT);
    cudaGetSymbolAddress((void**)&wmlp1T, g_wmlp1T);
    cudaGetSymbolAddress((void**)&wmlp2T, g_wmlp2T);

    cudaFuncSetAttribute(gemm_bf16<4,1>, cudaFuncAttributeMaxDynamicSharedMemorySize, GS_TOTAL);
    cudaFuncSetAttribute(gemm_bf16<1,1>, cudaFuncAttributeMaxDynamicSharedMemorySize, GS_TOTAL);
    cudaFuncSetAttribute(gemm_bf16<5,2>, cudaFuncAttributeMaxDynamicSharedMemorySize, GS_TOTAL);
    cudaFuncSetAttribute(gemm_bf16<5,4>, cudaFuncAttributeMaxDynamicSharedMemorySize, GS_TOTAL);

    static cudaStream_t sA = nullptr, sB = nullptr, sW = nullptr;
    static cudaEvent_t  e0 = nullptr, eW = nullptr, eA = nullptr, eB = nullptr;
    if (!sA) {
        cudaStreamCreateWithFlags(&sA, cudaStreamNonBlocking);
        cudaStreamCreateWithFlags(&sB, cudaStreamNonBlocking);
        cudaStreamCreateWithFlags(&sW, cudaStreamNonBlocking);
        cudaEventCreateWithFlags(&e0, cudaEventDisableTiming);
        cudaEventCreateWithFlags(&eW, cudaEventDisableTiming);
        cudaEventCreateWithFlags(&eA, cudaEventDisableTiming);
        cudaEventCreateWithFlags(&eB, cudaEventDisableTiming);
    }

    // fork
    cudaEventRecord(e0, 0);
    cudaStreamWaitEvent(sA, e0, 0);
    cudaStreamWaitEvent(sB, e0, 0);
    cudaStreamWaitEvent(sW, e0, 0);

    // weight conversions on sW
    wconv_kernel<<<dim3(3*CH/32, CH/64),  dim3(32,8), 0, sW>>>(w_qkv,  wqkvT,  CH,   3*CH);
    wconv_kernel<<<dim3(CH/32,   CH/64),  dim3(32,8), 0, sW>>>(w_proj, wprojT, CH,   CH);
    wconv_kernel<<<dim3(MLPC/32, CH/64),  dim3(32,8), 0, sW>>>(w_mlp1, wmlp1T, CH,   MLPC);
    wconv_kernel<<<dim3(CH/32,   MLPC/64),dim3(32,8), 0, sW>>>(w_mlp2, wmlp2T, MLPC, CH);
    cudaEventRecord(eW, sW);

    cudaStream_t cs[2] = {sA, sB};
    for (int ck = 0; ck < 2; ck++) {
        cudaStream_t st = cs[ck];
        const size_t to  = (size_t)ck * CTOK;          // token offset
        __nv_bfloat16* snh_c  = snh  + to * CH;
        __nv_bfloat16* qkv_c  = qkvh + to * 3*CH;
        __nv_bfloat16* att_c  = atth + to * CH;
        float*         y0_c   = y0   + to * CH;
        __nv_bfloat16* y0h_c  = y0h  + to * CH;
        __nv_bfloat16* mlp_c  = mlph + to * MLPC;
        float*         part_c = part + (size_t)ck * 4 * CTOK * CH;
        const float*   x_c    = x + (size_t)ck * 2 * CH * TLEN * 64;
        float*         y_c    = y + (size_t)ck * 2 * CH * TLEN * 64;

        meanln_kernel<<<CTOK, 256, 0, st>>>(x, ln_g, ln_b, snh, ck * 2);
        cudaStreamWaitEvent(st, eW, 0);

        // qkv: 2000 x 2304
        gemm_bf16<4,1><<<dim3(3*CH/128, 16), 256, GS_TOTAL, st>>>(
            snh_c, wqkvT, b_qkv, nullptr, qkv_c, CTOK, 3*CH, CH);
        attn_kernel<<<dim3(NWIN, HEADS, 2), 256, 0, st>>>(qkv_c, tau, att_c);

        // proj: 2000 x 768, split-K 2
        gemm_bf16<5,2><<<dim3(CH/128, 16, 2), 256, GS_TOTAL, st>>>(
            att_c, wprojT, nullptr, part_c, nullptr, CTOK, CH, CH);
        reduce_proj_kernel<<<(CTOK*CH/4 + 255)/256, 256, 0, st>>>(part_c, b_proj, y0_c, y0h_c);

        // mlp1 + gelu: 2000 x 3072
        gemm_bf16<1,1><<<dim3(MLPC/128, 16), 256, GS_TOTAL, st>>>(
            y0h_c, wmlp1T, b_mlp1, nullptr, mlp_c, CTOK, MLPC, CH);
        // mlp2: 2000 x 768, split-K 4 -> partials consumed directly by final
        gemm_bf16<5,4><<<dim3(CH/128, 16, 4), 256, GS_TOTAL, st>>>(
            mlp_c, wmlp2T, nullptr, part_c, nullptr, CTOK, CH, MLPC);

        // fused: mlp2-reduce + bias + residual + broadcast add
        final_fused_kernel<<<(2*CH*TLEN*16 + 255)/256, 256, 0, st>>>(
            x_c, part_c, b_mlp2, y0_c, y_c);
    }

    // join
    cudaEventRecord(eA, sA);
    cudaEventRecord(eB, sB);
    cudaStreamWaitEvent(0, eA, 0);
    cudaStreamWaitEvent(0, eB, 0);
}

// round 15
// speedup vs baseline: 1.0271x; 1.0007x over previous
#include <cuda_runtime.h>
#include <cuda_bf16.h>
#include <cstdint>

// ---------------------------------------------------------------------------
// Problem constants
// ---------------------------------------------------------------------------
#define BATCH 4
#define CH    768
#define TLEN  1000
#define HEADS 12
#define HDIM  64
#define WSZ   16
#define NWIN  63
#define NTOK  (BATCH*TLEN)       // 4000
#define MLPC  (4*CH)             // 3072
#define CTOK  2000               // tokens per chunk (2 batches)

// ---------------------------------------------------------------------------
// Scratch (device globals; allocation-free)
// ---------------------------------------------------------------------------
__device__ __nv_bfloat16  g_snh [NTOK*CH];
__device__ __nv_bfloat16  g_qkvh[NTOK*3*CH];
__device__ __nv_bfloat16  g_atth[NTOK*CH];
__device__ float          g_y0  [NTOK*CH];
__device__ __nv_bfloat16  g_y0h [NTOK*CH];
__device__ __nv_bfloat16  g_mlph[NTOK*MLPC];
__device__ float          g_o   [NTOK*CH];
__device__ __nv_bfloat16  g_wqkvT [3*CH*CH];
__device__ __nv_bfloat16  g_wprojT[CH*CH];
__device__ __nv_bfloat16  g_wmlp1T[MLPC*CH];
__device__ __nv_bfloat16  g_wmlp2T[CH*MLPC];

// ---------------------------------------------------------------------------
// Helpers
// ---------------------------------------------------------------------------
__device__ __forceinline__ uint32_t smem_u32(const void* p) {
    uint32_t a;
    asm("{ .reg .u64 t; cvta.to.shared.u64 t, %1; cvt.u32.u64 %0, t; }" : "=r"(a) : "l"(p));
    return a;
}

__device__ __forceinline__ void mma_bf16(float* c, const uint32_t* a, const uint32_t* b) {
    asm volatile(
        "mma.sync.aligned.m16n8k16.row.col.f32.bf16.bf16.f32 "
        "{%0,%1,%2,%3},{%4,%5,%6,%7},{%8,%9},{%0,%1,%2,%3};"
        : "+f"(c[0]), "+f"(c[1]), "+f"(c[2]), "+f"(c[3])
        : "r"(a[0]), "r"(a[1]), "r"(a[2]), "r"(a[3]), "r"(b[0]), "r"(b[1]));
}

__device__ __forceinline__ void cp_async16_sh(uint32_t dst, const void* src, int n) {
    asm volatile("cp.async.cg.shared.global [%0], [%1], 16, %2;"
                 :: "r"(dst), "l"(src), "r"(n));
}

#define LDSM_X4(r0, r1, r2, r3, addr)                                         \
    asm volatile("ldmatrix.sync.aligned.m8n8.x4.shared.b16 {%0,%1,%2,%3}, [%4];" \
                 : "=r"(r0), "=r"(r1), "=r"(r2), "=r"(r3) : "r"(addr))

// ---------------------------------------------------------------------------
// K1: fused spatial mean + LayerNorm.  One block per token; b0 = batch offset.
// ---------------------------------------------------------------------------
__global__ __launch_bounds__(256)
void meanln_kernel(const float* __restrict__ x, const float* __restrict__ gg,
                   const float* __restrict__ bb, __nv_bfloat16* __restrict__ sn,
                   int b0) {
    __shared__ float red[2][8];
    int tokl = blockIdx.x;             // 0..CTOK-1
    int b    = b0 + tokl / TLEN;
    int t    = tokl % TLEN;
    int tid  = threadIdx.x;            // 256

    float sval[3];
    float psum = 0.f, psq = 0.f;
    #pragma unroll
    for (int j = 0; j < 3; j++) {
        int c = tid + j * 256;
        const float4* p = reinterpret_cast<const float4*>(
            x + ((size_t)(b * CH + c) * TLEN + t) * 64);
        float acc = 0.f;
        #pragma unroll
        for (int i = 0; i < 16; i++) {
            float4 v = p[i];
            acc += (v.x + v.y) + (v.z + v.w);
        }
        float s = acc * (1.0f/64.0f);
        sval[j] = s;
        psum += s;
        psq  += s * s;
    }
    #pragma unroll
    for (int m = 16; m; m >>= 1) {
        psum += __shfl_xor_sync(0xffffffffu, psum, m);
        psq  += __shfl_xor_sync(0xffffffffu, psq,  m);
    }
    if ((tid & 31) == 0) { red[0][tid>>5] = psum; red[1][tid>>5] = psq; }
    __syncthreads();
    if (tid < 32) {
        float a  = (tid < 8) ? red[0][tid] : 0.f;
        float b2 = (tid < 8) ? red[1][tid] : 0.f;
        #pragma unroll
        for (int m = 4; m; m >>= 1) {
            a  += __shfl_xor_sync(0xffffffffu, a,  m);
            b2 += __shfl_xor_sync(0xffffffffu, b2, m);
        }
        if (tid == 0) { red[0][0] = a; red[1][0] = b2; }
    }
    __syncthreads();
    float mean = red[0][0] * (1.0f/768.0f);
    float var  = red[1][0] * (1.0f/768.0f) - mean*mean;
    float rstd = rsqrtf(var + 1e-5f);
    __nv_bfloat16* orow = sn + ((size_t)b * TLEN + t) * CH;
    #pragma unroll
    for (int j = 0; j < 3; j++) {
        int c = tid + j * 256;
        orow[c] = __float2bfloat16((sval[j]-mean)*rstd*gg[c] + bb[c]);
    }
}

// ---------------------------------------------------------------------------
// K3: weight convert + transpose.  W fp32 [K][N] -> WT bf16 [N][K]
// ---------------------------------------------------------------------------
__global__ void wconv_kernel(const float* __restrict__ W, __nv_bfloat16* __restrict__ WT,
                             int K, int N) {
    __shared__ float t[64][33];
    int bx = blockIdx.x * 32;   // n base
    int by = blockIdx.y * 64;   // k base
    int tx = threadIdx.x, ty = threadIdx.y;    // 32 x 8
    #pragma unroll
    for (int i = ty; i < 64; i += 8)
        t[i][tx] = W[(size_t)(by + i) * N + bx + tx];
    __syncthreads();
    #pragma unroll
    for (int i = ty; i < 32; i += 8) {
        __nv_bfloat162 h = __floats2bfloat162_rn(t[2*tx][i], t[2*tx+1][i]);
        *reinterpret_cast<__nv_bfloat162*>(WT + (size_t)(bx + i) * K + by + 2*tx) = h;
    }
}

// ---------------------------------------------------------------------------
// GEMM: C = A(MxK,bf16 row-major) @ BT(NxK,bf16 K-major)^T + bias
// bf16 mma.sync m16n8k16, block 128x128x64, 8 warps (2x4), warp tile 64x32.
// 2-stage cp.async, 1 barrier per 64-K slice, ldmatrix.x4 (72-half stride).
// EPI: 1 = bias + exact GELU -> bf16 Ch
//      2 = bias + residual(fp32 Res) -> fp32 C
//      3 = bias -> fp32 C and bf16 Ch
//      4 = bias -> bf16 Ch
// ---------------------------------------------------------------------------
#define GS_OPER   18432u
#define GS_STAGE  36864u
#define GS_TOTAL  73728

template<int EPI>
__global__ __launch_bounds__(256, 2)
void gemm_bf16(const __nv_bfloat16* __restrict__ A, const __nv_bfloat16* __restrict__ BT,
               const float* __restrict__ bias, const float* __restrict__ Res,
               float* __restrict__ C, __nv_bfloat16* __restrict__ Ch,
               int M, int N, int K)
{
    extern __shared__ __nv_bfloat16 smem[];
    const uint32_t smemu = smem_u32(smem);

    int tid  = threadIdx.x;
    int lane = tid & 31, warp = tid >> 5;
    int wm = warp >> 2, wn = warp & 3;
    int bm = blockIdx.y * 128, bn = blockIdx.x * 128;
    int g  = lane >> 2, tg = lane & 3;

    const int KT = K >> 6;

    int crow  = tid >> 1;
    int coffh = (tid & 1) * 32;
    int arow = bm + crow; if (arow > M-1) arow = M-1;
    int aok  = (bm + crow < M) ? 16 : 0;
    const __nv_bfloat16* gA = A  + (size_t)arow      * K + coffh;
    const __nv_bfloat16* gB = BT + (size_t)(bn+crow) * K + coffh;
    const uint32_t dstOff = (uint32_t)crow * 144u + (uint32_t)coffh * 2u;

    const uint32_t aFrag = (uint32_t)(wm*64 + (lane & 7) + ((lane >> 3) & 1) * 8) * 144u
                         + (uint32_t)((lane >> 4) * 8) * 2u;
    const uint32_t bFrag = (uint32_t)(wn*32 + (lane & 7) + ((lane >> 4) & 1) * 8) * 144u
                         + (uint32_t)(((lane >> 3) & 1) * 8) * 2u;

    float acc[4][4][4];
    #pragma unroll
    for (int i = 0; i < 4; i++)
        #pragma unroll
        for (int j = 0; j < 4; j++)
            #pragma unroll
            for (int r = 0; r < 4; r++) acc[i][j][r] = 0.f;

    auto prefetch = [&](int c) {
        uint32_t da = smemu + (uint32_t)(c & 1) * GS_STAGE + dstOff;
        uint32_t db = da + GS_OPER;
        const __nv_bfloat16* sa = gA + c * 64;
        const __nv_bfloat16* sb = gB + c * 64;
        #pragma unroll
        for (int j = 0; j < 4; j++) {
            cp_async16_sh(da + j*16u, sa + j*8, aok);
            cp_async16_sh(db + j*16u, sb + j*8, 16);
        }
        asm volatile("cp.async.commit_group;");
    };

    prefetch(0);

    for (int kt = 0; kt < KT; kt++) {
        asm volatile("cp.async.wait_group 0;");
        __syncthreads();
        if (kt + 1 < KT) prefetch(kt + 1);

        uint32_t aB = smemu + (uint32_t)(kt & 1) * GS_STAGE + aFrag;
        uint32_t bB = aB - aFrag + GS_OPER + bFrag;
        #pragma unroll
        for (int kk = 0; kk < 4; kk++) {
            uint32_t kby = (uint32_t)kk * 32u;
            uint32_t af[4][4], bf[4][2];
            #pragma unroll
            for (int mi = 0; mi < 4; mi++)
                LDSM_X4(af[mi][0], af[mi][1], af[mi][2], af[mi][3],
                        aB + (uint32_t)mi * (16u*144u) + kby);
            #pragma unroll
            for (int p = 0; p < 2; p++)
                LDSM_X4(bf[2*p][0], bf[2*p][1], bf[2*p+1][0], bf[2*p+1][1],
                        bB + (uint32_t)p * (16u*144u) + kby);
            #pragma unroll
            for (int mi = 0; mi < 4; mi++)
                #pragma unroll
                for (int ni = 0; ni < 4; ni++)
                    mma_bf16(acc[mi][ni], af[mi], bf[ni]);
        }
    }

    // ---- epilogue ----
    #pragma unroll
    for (int mi = 0; mi < 4; mi++) {
        int r0 = bm + wm*64 + mi*16 + g;
        #pragma unroll
        for (int ni = 0; ni < 4; ni++) {
            int c0 = bn + wn*32 + ni*8 + 2*tg;
            float b0 = bias[c0], b1 = bias[c0+1];
            #pragma unroll
            for (int half = 0; half < 2; half++) {
                int r = r0 + half*8;
                if (r < M) {
                    float v0 = acc[mi][ni][half*2]   + b0;
                    float v1 = acc[mi][ni][half*2+1] + b1;
                    if (EPI == 1) { v0 = v0 * normcdff(v0); v1 = v1 * normcdff(v1); }
                    if (EPI == 2) {
                        const float2 rr = *reinterpret_cast<const float2*>(Res + (size_t)r*N + c0);
                        v0 += rr.x; v1 += rr.y;
                    }
                    if (EPI == 2 || EPI == 3)
                        *reinterpret_cast<float2*>(C + (size_t)r*N + c0) = make_float2(v0, v1);
                    if (EPI == 1 || EPI == 3 || EPI == 4)
                        *reinterpret_cast<__nv_bfloat162*>(Ch + (size_t)r*N + c0) =
                            __floats2bfloat162_rn(v0, v1);
                }
            }
        }
    }
}

// ---------------------------------------------------------------------------
// K4: windowed cosine attention (bf16 in, bf16 out). Pointers pre-offset
// to chunk; blockIdx.z = local batch.
// ---------------------------------------------------------------------------
__global__ void attn_kernel(const __nv_bfloat16* __restrict__ qkv,
                            const float* __restrict__ tau,
                            __nv_bfloat16* __restrict__ att) {
    __shared__ float qs[16][68], ks[16][68], vs[16][68];
    __shared__ float rq[16], rk[16];
    __shared__ float at[16][17];
    __shared__ float tauv;

    int n = blockIdx.x, hh = blockIdx.y, b = blockIdx.z;
    int tid = threadIdx.x;                  // 256

    {
        int rr  = tid >> 4;
        int c4 = (tid & 15) << 2;
        int t  = n*WSZ + rr;
        float4 q4 = make_float4(0.f,0.f,0.f,0.f), k4 = q4, v4 = q4;
        if (t < TLEN) {
            size_t bb = (size_t)(b*TLEN + t) * (3*CH) + hh*HDIM + c4;
            uint2 qu = *reinterpret_cast<const uint2*>(qkv + bb);
            uint2 ku = *reinterpret_cast<const uint2*>(qkv + bb + CH);
            uint2 vu = *reinterpret_cast<const uint2*>(qkv + bb + 2*CH);
            float2 a0 = __bfloat1622float2(*reinterpret_cast<__nv_bfloat162*>(&qu.x));
            float2 a1 = __bfloat1622float2(*reinterpret_cast<__nv_bfloat162*>(&qu.y));
            q4 = make_float4(a0.x, a0.y, a1.x, a1.y);
            a0 = __bfloat1622float2(*reinterpret_cast<__nv_bfloat162*>(&ku.x));
            a1 = __bfloat1622float2(*reinterpret_cast<__nv_bfloat162*>(&ku.y));
            k4 = make_float4(a0.x, a0.y, a1.x, a1.y);
            a0 = __bfloat1622float2(*reinterpret_cast<__nv_bfloat162*>(&vu.x));
            a1 = __bfloat1622float2(*reinterpret_cast<__nv_bfloat162*>(&vu.y));
            v4 = make_float4(a0.x, a0.y, a1.x, a1.y);
        }
        *reinterpret_cast<float4*>(&qs[rr][c4]) = q4;
        *reinterpret_cast<float4*>(&ks[rr][c4]) = k4;
        *reinterpret_cast<float4*>(&vs[rr][c4]) = v4;
        if (tid == 0) tauv = tau[hh] + 1e-6f;
    }
    __syncthreads();

    if (tid < 32) {
        const float* p = (tid < 16) ? &qs[tid][0] : &ks[tid-16][0];
        float ssum = 0.f;
        #pragma unroll
        for (int i = 0; i < 64; i++) ssum += p[i]*p[i];
        float inv = 1.0f / fmaxf(sqrtf(ssum), 1e-12f);
        if (tid < 16) rq[tid] = inv; else rk[tid-16] = inv;
    }
    __syncthreads();

    int w  = tid >> 4;
    int s2 = tid & 15;
    float dot = 0.f;
    #pragma unroll
    for (int i = 0; i < 64; i++) dot += qs[w][i] * ks[s2][i];
    float logit = dot * rq[w] * rk[s2] / tauv;

    float mx = logit;
    #pragma unroll
    for (int m = 8; m; m >>= 1) mx = fmaxf(mx, __shfl_xor_sync(0xffffffffu, mx, m));
    float e = expf(logit - mx);
    float ssum = e;
    #pragma unroll
    for (int m = 8; m; m >>= 1) ssum += __shfl_xor_sync(0xffffffffu, ssum, m);
    at[w][s2] = e / ssum;
    __syncthreads();

    int c0 = (tid & 15) << 2;
    float o0=0.f, o1=0.f, o2=0.f, o3=0.f;
    #pragma unroll
    for (int ss = 0; ss < 16; ss++) {
        float a = at[w][ss];
        o0 += a * vs[ss][c0+0];
        o1 += a * vs[ss][c0+1];
        o2 += a * vs[ss][c0+2];
        o3 += a * vs[ss][c0+3];
    }
    int t = n*WSZ + w;
    if (t < TLEN) {
        __nv_bfloat16* dst = att + (size_t)(b*TLEN + t)*CH + hh*HDIM + c0;
        *reinterpret_cast<__nv_bfloat162*>(dst)     = __floats2bfloat162_rn(o0, o1);
        *reinterpret_cast<__nv_bfloat162*>(dst + 2) = __floats2bfloat162_rn(o2, o3);
    }
}

// ---------------------------------------------------------------------------
// K8: y = x + o*0.5 broadcast. Pointers pre-offset to chunk (2 batches).
// ---------------------------------------------------------------------------
__global__ void final_kernel(const float* __restrict__ x, const float* __restrict__ o,
                             float* __restrict__ y) {
    unsigned i4 = blockIdx.x * 256u + threadIdx.x;    // over 2*CH*TLEN*16 float4
    if (i4 >= (unsigned)(2*CH*TLEN*16)) return;
    unsigned row = i4 >> 4;              // (b_local, c, t)
    unsigned t  = row % TLEN;
    unsigned bc = row / TLEN;
    unsigned c  = bc % CH;
    unsigned b  = bc / CH;               // 0..1
    float val = __ldg(o + (size_t)(b*TLEN + t)*CH + c) * 0.5f;
    float4 xv = reinterpret_cast<const float4*>(x)[i4];
    xv.x += val; xv.y += val; xv.z += val; xv.w += val;
    reinterpret_cast<float4*>(y)[i4] = xv;
}

// ---------------------------------------------------------------------------
// Launch: two independent token-chunk pipelines on two streams
// (R11 topology, split-K removed — direct GEMM epilogues).
// ---------------------------------------------------------------------------
extern "C" void kernel_launch(void* const* d_in, const int* in_sizes, int n_in,
                              void* d_out, int out_size) {
    const float* x      = (const float*)d_in[0];
    const float* ln_g   = (const float*)d_in[1];
    const float* ln_b   = (const float*)d_in[2];
    const float* tau    = (const float*)d_in[3];
    const float* w_qkv  = (const float*)d_in[4];
    const float* b_qkv  = (const float*)d_in[5];
    const float* w_proj = (const float*)d_in[6];
    const float* b_proj = (const float*)d_in[7];
    const float* w_mlp1 = (const float*)d_in[8];
    const float* b_mlp1 = (const float*)d_in[9];
    const float* w_mlp2 = (const float*)d_in[10];
    const float* b_mlp2 = (const float*)d_in[11];
    float* y = (float*)d_out;

    float *y0, *o;
    __nv_bfloat16 *snh, *qkvh, *atth, *y0h, *mlph, *wqkvT, *wprojT, *wmlp1T, *wmlp2T;
    cudaGetSymbolAddress((void**)&snh,    g_snh);
    cudaGetSymbolAddress((void**)&qkvh,   g_qkvh);
    cudaGetSymbolAddress((void**)&atth,   g_atth);
    cudaGetSymbolAddress((void**)&y0,     g_y0);
    cudaGetSymbolAddress((void**)&y0h,    g_y0h);
    cudaGetSymbolAddress((void**)&mlph,   g_mlph);
    cudaGetSymbolAddress((void**)&o,      g_o);
    cudaGetSymbolAddress((void**)&wqkvT,  g_wqkvT);
    cudaGetSymbolAddress((void**)&wprojT, g_wprojT);
    cudaGetSymbolAddress((void**)&wmlp1T, g_wmlp1T);
    cudaGetSymbolAddress((void**)&wmlp2T, g_wmlp2T);

    cudaFuncSetAttribute(gemm_bf16<1>, cudaFuncAttributeMaxDynamicSharedMemorySize, GS_TOTAL);
    cudaFuncSetAttribute(gemm_bf16<2>, cudaFuncAttributeMaxDynamicSharedMemorySize, GS_TOTAL);
    cudaFuncSetAttribute(gemm_bf16<3>, cudaFuncAttributeMaxDynamicSharedMemorySize, GS_TOTAL);
    cudaFuncSetAttribute(gemm_bf16<4>, cudaFuncAttributeMaxDynamicSharedMemorySize, GS_TOTAL);

    static cudaStream_t sA = nullptr, sB = nullptr, sW = nullptr;
    static cudaEvent_t  e0 = nullptr, eW = nullptr, eA = nullptr, eB = nullptr;
    if (!sA) {
        cudaStreamCreateWithFlags(&sA, cudaStreamNonBlocking);
        cudaStreamCreateWithFlags(&sB, cudaStreamNonBlocking);
        cudaStreamCreateWithFlags(&sW, cudaStreamNonBlocking);
        cudaEventCreateWithFlags(&e0, cudaEventDisableTiming);
        cudaEventCreateWithFlags(&eW, cudaEventDisableTiming);
        cudaEventCreateWithFlags(&eA, cudaEventDisableTiming);
        cudaEventCreateWithFlags(&eB, cudaEventDisableTiming);
    }

    // fork
    cudaEventRecord(e0, 0);
    cudaStreamWaitEvent(sA, e0, 0);
    cudaStreamWaitEvent(sB, e0, 0);
    cudaStreamWaitEvent(sW, e0, 0);

    // weight conversions on sW
    wconv_kernel<<<dim3(3*CH/32, CH/64),  dim3(32,8), 0, sW>>>(w_qkv,  wqkvT,  CH,   3*CH);
    wconv_kernel<<<dim3(CH/32,   CH/64),  dim3(32,8), 0, sW>>>(w_proj, wprojT, CH,   CH);
    wconv_kernel<<<dim3(MLPC/32, CH/64),  dim3(32,8), 0, sW>>>(w_mlp1, wmlp1T, CH,   MLPC);
    wconv_kernel<<<dim3(CH/32,   MLPC/64),dim3(32,8), 0, sW>>>(w_mlp2, wmlp2T, MLPC, CH);
    cudaEventRecord(eW, sW);

    cudaStream_t cs[2] = {sA, sB};
    for (int ck = 0; ck < 2; ck++) {
        cudaStream_t st = cs[ck];
        const size_t to  = (size_t)ck * CTOK;          // token offset
        __nv_bfloat16* snh_c  = snh  + to * CH;
        __nv_bfloat16* qkv_c  = qkvh + to * 3*CH;
        __nv_bfloat16* att_c  = atth + to * CH;
        float*         y0_c   = y0   + to * CH;
        __nv_bfloat16* y0h_c  = y0h  + to * CH;
        __nv_bfloat16* mlp_c  = mlph + to * MLPC;
        float*         o_c    = o    + to * CH;
        const float*   x_c    = x + (size_t)ck * 2 * CH * TLEN * 64;
        float*         y_c    = y + (size_t)ck * 2 * CH * TLEN * 64;

        meanln_kernel<<<CTOK, 256, 0, st>>>(x, ln_g, ln_b, snh, ck * 2);
        cudaStreamWaitEvent(st, eW, 0);

        // qkv: 2000 x 2304 -> bf16
        gemm_bf16<4><<<dim3(3*CH/128, 16), 256, GS_TOTAL, st>>>(
            snh_c, wqkvT, b_qkv, nullptr, nullptr, qkv_c, CTOK, 3*CH, CH);
        attn_kernel<<<dim3(NWIN, HEADS, 2), 256, 0, st>>>(qkv_c, tau, att_c);

        // proj: 2000 x 768 -> fp32 y0 + bf16 y0h (direct, no split-K)
        gemm_bf16<3><<<dim3(CH/128, 16), 256, GS_TOTAL, st>>>(
            att_c, wprojT, b_proj, nullptr, y0_c, y0h_c, CTOK, CH, CH);

        // mlp1 + gelu: 2000 x 3072 -> bf16
        gemm_bf16<1><<<dim3(MLPC/128, 16), 256, GS_TOTAL, st>>>(
            y0h_c, wmlp1T, b_mlp1, nullptr, nullptr, mlp_c, CTOK, MLPC, CH);

        // mlp2 + residual: 2000 x 768 -> fp32 o (direct, no split-K)
        gemm_bf16<2><<<dim3(CH/128, 16), 256, GS_TOTAL, st>>>(
            mlp_c, wmlp2T, b_mlp2, y0_c, o_c, nullptr, CTOK, CH, MLPC);

        final_kernel<<<(2*CH*TLEN*16 + 255)/256, 256, 0, st>>>(x_c, o_c, y_c);
    }

    // join
    cudaEventRecord(eA, sA);
    cudaEventRecord(eB, sB);
    cudaStreamWaitEvent(0, eA, 0);
    cudaStreamWaitEvent(0, eB, 0);
}

// round 16
// speedup vs baseline: 1.0362x; 1.0088x over previous
#include <cuda_runtime.h>
#include <cuda_bf16.h>
#include <cstdint>

// ---------------------------------------------------------------------------
// Problem constants
// ---------------------------------------------------------------------------
#define BATCH 4
#define CH    768
#define TLEN  1000
#define HEADS 12
#define HDIM  64
#define WSZ   16
#define NWIN  63
#define NTOK  (BATCH*TLEN)       // 4000
#define MLPC  (4*CH)             // 3072
#define CTOK  2000               // tokens per chunk (2 batches)

// ---------------------------------------------------------------------------
// Scratch (device globals; allocation-free)
// ---------------------------------------------------------------------------
__device__ __nv_bfloat16  g_snh [NTOK*CH];
__device__ __nv_bfloat16  g_qkvh[NTOK*3*CH];
__device__ __nv_bfloat16  g_atth[NTOK*CH];
__device__ float          g_y0  [NTOK*CH];
__device__ __nv_bfloat16  g_y0h [NTOK*CH];
__device__ __nv_bfloat16  g_mlph[NTOK*MLPC];
__device__ float          g_o   [NTOK*CH];
__device__ float          g_part[4*NTOK*CH];      // [chunk][4][CTOK][CH]
__device__ __nv_bfloat16  g_wqkvT [3*CH*CH];
__device__ __nv_bfloat16  g_wprojT[CH*CH];
__device__ __nv_bfloat16  g_wmlp1T[MLPC*CH];
__device__ __nv_bfloat16  g_wmlp2T[CH*MLPC];

// ---------------------------------------------------------------------------
// Helpers
// ---------------------------------------------------------------------------
__device__ __forceinline__ uint32_t smem_u32(const void* p) {
    uint32_t a;
    asm("{ .reg .u64 t; cvta.to.shared.u64 t, %1; cvt.u32.u64 %0, t; }" : "=r"(a) : "l"(p));
    return a;
}

__device__ __forceinline__ void mma_bf16(float* c, const uint32_t* a, const uint32_t* b) {
    asm volatile(
        "mma.sync.aligned.m16n8k16.row.col.f32.bf16.bf16.f32 "
        "{%0,%1,%2,%3},{%4,%5,%6,%7},{%8,%9},{%0,%1,%2,%3};"
        : "+f"(c[0]), "+f"(c[1]), "+f"(c[2]), "+f"(c[3])
        : "r"(a[0]), "r"(a[1]), "r"(a[2]), "r"(a[3]), "r"(b[0]), "r"(b[1]));
}

__device__ __forceinline__ void cp_async16_sh(uint32_t dst, const void* src, int n) {
    asm volatile("cp.async.cg.shared.global [%0], [%1], 16, %2;"
                 :: "r"(dst), "l"(src), "r"(n));
}

#define LDSM_X4(r0, r1, r2, r3, addr)                                         \
    asm volatile("ldmatrix.sync.aligned.m8n8.x4.shared.b16 {%0,%1,%2,%3}, [%4];" \
                 : "=r"(r0), "=r"(r1), "=r"(r2), "=r"(r3) : "r"(addr))

// ---------------------------------------------------------------------------
// K1: fused spatial mean + LayerNorm.  One block per token; b0 = batch offset.
// ---------------------------------------------------------------------------
__global__ __launch_bounds__(256)
void meanln_kernel(const float* __restrict__ x, const float* __restrict__ gg,
                   const float* __restrict__ bb, __nv_bfloat16* __restrict__ sn,
                   int b0) {
    __shared__ float red[2][8];
    int tokl = blockIdx.x;             // 0..CTOK-1
    int b    = b0 + tokl / TLEN;
    int t    = tokl % TLEN;
    int tid  = threadIdx.x;            // 256

    float sval[3];
    float psum = 0.f, psq = 0.f;
    #pragma unroll
    for (int j = 0; j < 3; j++) {
        int c = tid + j * 256;
        const float4* p = reinterpret_cast<const float4*>(
            x + ((size_t)(b * CH + c) * TLEN + t) * 64);
        float acc = 0.f;
        #pragma unroll
        for (int i = 0; i < 16; i++) {
            float4 v = p[i];
            acc += (v.x + v.y) + (v.z + v.w);
        }
        float s = acc * (1.0f/64.0f);
        sval[j] = s;
        psum += s;
        psq  += s * s;
    }
    #pragma unroll
    for (int m = 16; m; m >>= 1) {
        psum += __shfl_xor_sync(0xffffffffu, psum, m);
        psq  += __shfl_xor_sync(0xffffffffu, psq,  m);
    }
    if ((tid & 31) == 0) { red[0][tid>>5] = psum; red[1][tid>>5] = psq; }
    __syncthreads();
    if (tid < 32) {
        float a  = (tid < 8) ? red[0][tid] : 0.f;
        float b2 = (tid < 8) ? red[1][tid] : 0.f;
        #pragma unroll
        for (int m = 4; m; m >>= 1) {
            a  += __shfl_xor_sync(0xffffffffu, a,  m);
            b2 += __shfl_xor_sync(0xffffffffu, b2, m);
        }
        if (tid == 0) { red[0][0] = a; red[1][0] = b2; }
    }
    __syncthreads();
    float mean = red[0][0] * (1.0f/768.0f);
    float var  = red[1][0] * (1.0f/768.0f) - mean*mean;
    float rstd = rsqrtf(var + 1e-5f);
    __nv_bfloat16* orow = sn + ((size_t)b * TLEN + t) * CH;
    #pragma unroll
    for (int j = 0; j < 3; j++) {
        int c = tid + j * 256;
        orow[c] = __float2bfloat16((sval[j]-mean)*rstd*gg[c] + bb[c]);
    }
}

// ---------------------------------------------------------------------------
// K3: weight convert + transpose.  W fp32 [K][N] -> WT bf16 [N][K]
// ---------------------------------------------------------------------------
__global__ void wconv_kernel(const float* __restrict__ W, __nv_bfloat16* __restrict__ WT,
                             int K, int N) {
    __shared__ float t[64][33];
    int bx = blockIdx.x * 32;   // n base
    int by = blockIdx.y * 64;   // k base
    int tx = threadIdx.x, ty = threadIdx.y;    // 32 x 8
    #pragma unroll
    for (int i = ty; i < 64; i += 8)
        t[i][tx] = W[(size_t)(by + i) * N + bx + tx];
    __syncthreads();
    #pragma unroll
    for (int i = ty; i < 32; i += 8) {
        __nv_bfloat162 h = __floats2bfloat162_rn(t[2*tx][i], t[2*tx+1][i]);
        *reinterpret_cast<__nv_bfloat162*>(WT + (size_t)(bx + i) * K + by + 2*tx) = h;
    }
}

// ---------------------------------------------------------------------------
// GEMM: C = A(MxK,bf16 row-major) @ BT(NxK,bf16 K-major)^T
// bf16 mma.sync m16n8k16, block 128x128x64, 8 warps (2x4), warp tile 64x32.
// 2-stage cp.async, 1 barrier per 64-K slice, ldmatrix.x4 (72-half stride).
// EPI: 1 = bias + exact GELU -> bf16 Ch
//      4 = bias -> bf16 Ch
//      5 = raw partial (no bias) -> fp32 C at split offset (blockIdx.z)
// ---------------------------------------------------------------------------
#define GS_OPER   18432u
#define GS_STAGE  36864u
#define GS_TOTAL  73728

template<int EPI, int SPLIT>
__global__ __launch_bounds__(256, 2)
void gemm_bf16(const __nv_bfloat16* __restrict__ A, const __nv_bfloat16* __restrict__ BT,
               const float* __restrict__ bias,
               float* __restrict__ C, __nv_bfloat16* __restrict__ Ch,
               int M, int N, int K)
{
    extern __shared__ __nv_bfloat16 smem[];
    const uint32_t smemu = smem_u32(smem);

    int tid  = threadIdx.x;
    int lane = tid & 31, warp = tid >> 5;
    int wm = warp >> 2, wn = warp & 3;
    int bm = blockIdx.y * 128, bn = blockIdx.x * 128;
    int g  = lane >> 2, tg = lane & 3;

    const int KTtot = K >> 6;
    const int per   = KTtot / SPLIT;
    const int kz    = (SPLIT > 1) ? blockIdx.z : 0;
    const int kt0   = kz * per;
    const int kt1   = kt0 + per;

    int crow  = tid >> 1;
    int coffh = (tid & 1) * 32;
    int arow = bm + crow; if (arow > M-1) arow = M-1;
    int aok  = (bm + crow < M) ? 16 : 0;
    const __nv_bfloat16* gA = A  + (size_t)arow      * K + coffh;
    const __nv_bfloat16* gB = BT + (size_t)(bn+crow) * K + coffh;
    const uint32_t dstOff = (uint32_t)crow * 144u + (uint32_t)coffh * 2u;

    const uint32_t aFrag = (uint32_t)(wm*64 + (lane & 7) + ((lane >> 3) & 1) * 8) * 144u
                         + (uint32_t)((lane >> 4) * 8) * 2u;
    const uint32_t bFrag = (uint32_t)(wn*32 + (lane & 7) + ((lane >> 4) & 1) * 8) * 144u
                         + (uint32_t)(((lane >> 3) & 1) * 8) * 2u;

    float acc[4][4][4];
    #pragma unroll
    for (int i = 0; i < 4; i++)
        #pragma unroll
        for (int j = 0; j < 4; j++)
            #pragma unroll
            for (int r = 0; r < 4; r++) acc[i][j][r] = 0.f;

    auto prefetch = [&](int c) {
        uint32_t da = smemu + (uint32_t)(c & 1) * GS_STAGE + dstOff;
        uint32_t db = da + GS_OPER;
        const __nv_bfloat16* sa = gA + c * 64;
        const __nv_bfloat16* sb = gB + c * 64;
        #pragma unroll
        for (int j = 0; j < 4; j++) {
            cp_async16_sh(da + j*16u, sa + j*8, aok);
            cp_async16_sh(db + j*16u, sb + j*8, 16);
        }
        asm volatile("cp.async.commit_group;");
    };

    prefetch(kt0);

    for (int kt = kt0; kt < kt1; kt++) {
        asm volatile("cp.async.wait_group 0;");
        __syncthreads();
        if (kt + 1 < kt1) prefetch(kt + 1);

        uint32_t aB = smemu + (uint32_t)(kt & 1) * GS_STAGE + aFrag;
        uint32_t bB = aB - aFrag + GS_OPER + bFrag;
        #pragma unroll
        for (int kk = 0; kk < 4; kk++) {
            uint32_t kby = (uint32_t)kk * 32u;
            uint32_t af[4][4], bf[4][2];
            #pragma unroll
            for (int mi = 0; mi < 4; mi++)
                LDSM_X4(af[mi][0], af[mi][1], af[mi][2], af[mi][3],
                        aB + (uint32_t)mi * (16u*144u) + kby);
            #pragma unroll
            for (int p = 0; p < 2; p++)
                LDSM_X4(bf[2*p][0], bf[2*p][1], bf[2*p+1][0], bf[2*p+1][1],
                        bB + (uint32_t)p * (16u*144u) + kby);
            #pragma unroll
            for (int mi = 0; mi < 4; mi++)
                #pragma unroll
                for (int ni = 0; ni < 4; ni++)
                    mma_bf16(acc[mi][ni], af[mi], bf[ni]);
        }
    }

    // ---- epilogue ----
    float* Cpart = (EPI == 5) ? (C + (size_t)kz * M * N) : C;
    #pragma unroll
    for (int mi = 0; mi < 4; mi++) {
        int r0 = bm + wm*64 + mi*16 + g;
        #pragma unroll
        for (int ni = 0; ni < 4; ni++) {
            int c0 = bn + wn*32 + ni*8 + 2*tg;
            float b0 = 0.f, b1 = 0.f;
            if (EPI != 5) { b0 = bias[c0]; b1 = bias[c0+1]; }
            #pragma unroll
            for (int half = 0; half < 2; half++) {
                int r = r0 + half*8;
                if (r < M) {
                    float v0 = acc[mi][ni][half*2]   + b0;
                    float v1 = acc[mi][ni][half*2+1] + b1;
                    if (EPI == 1) { v0 = v0 * normcdff(v0); v1 = v1 * normcdff(v1); }
                    if (EPI == 5)
                        *reinterpret_cast<float2*>(Cpart + (size_t)r*N + c0) = make_float2(v0, v1);
                    else
                        *reinterpret_cast<__nv_bfloat162*>(Ch + (size_t)r*N + c0) =
                            __floats2bfloat162_rn(v0, v1);
                }
            }
        }
    }
}

// ---------------------------------------------------------------------------
// Split-K reduce kernels (fixed-order sums -> deterministic). Per chunk.
// ---------------------------------------------------------------------------
__global__ void reduce_proj_kernel(const float* __restrict__ part,
                                   const float* __restrict__ bias,
                                   float* __restrict__ y0, __nv_bfloat16* __restrict__ y0h) {
    unsigned i = blockIdx.x * 256u + threadIdx.x;       // over CTOK*CH/4
    if (i >= (unsigned)(CTOK*CH/4)) return;
    const float4 p0 = reinterpret_cast<const float4*>(part)[i];
    const float4 p1 = reinterpret_cast<const float4*>(part + (size_t)CTOK*CH)[i];
    const float4 bv = reinterpret_cast<const float4*>(bias)[i % (CH/4)];
    float4 v;
    v.x = p0.x + p1.x + bv.x;
    v.y = p0.y + p1.y + bv.y;
    v.z = p0.z + p1.z + bv.z;
    v.w = p0.w + p1.w + bv.w;
    reinterpret_cast<float4*>(y0)[i] = v;
    reinterpret_cast<__nv_bfloat162*>(y0h)[2*i]   = __floats2bfloat162_rn(v.x, v.y);
    reinterpret_cast<__nv_bfloat162*>(y0h)[2*i+1] = __floats2bfloat162_rn(v.z, v.w);
}

__global__ void reduce_mlp2_kernel(const float* __restrict__ part,
                                   const float* __restrict__ bias,
                                   const float* __restrict__ y0,
                                   float* __restrict__ o) {
    unsigned i = blockIdx.x * 256u + threadIdx.x;       // over CTOK*CH/4
    if (i >= (unsigned)(CTOK*CH/4)) return;
    const size_t str = (size_t)CTOK*CH;
    const float4 p0 = reinterpret_cast<const float4*>(part)[i];
    const float4 p1 = reinterpret_cast<const float4*>(part + str)[i];
    const float4 p2 = reinterpret_cast<const float4*>(part + 2*str)[i];
    const float4 p3 = reinterpret_cast<const float4*>(part + 3*str)[i];
    const float4 bv = reinterpret_cast<const float4*>(bias)[i % (CH/4)];
    const float4 rv = reinterpret_cast<const float4*>(y0)[i];
    float4 v;
    v.x = ((p0.x + p1.x) + (p2.x + p3.x)) + bv.x + rv.x;
    v.y = ((p0.y + p1.y) + (p2.y + p3.y)) + bv.y + rv.y;
    v.z = ((p0.z + p1.z) + (p2.z + p3.z)) + bv.z + rv.z;
    v.w = ((p0.w + p1.w) + (p2.w + p3.w)) + bv.w + rv.w;
    reinterpret_cast<float4*>(o)[i] = v;
}

// ---------------------------------------------------------------------------
// K4: windowed cosine attention (bf16 in, bf16 out). Pointers pre-offset
// to chunk; blockIdx.z = local batch.
// ---------------------------------------------------------------------------
__global__ void attn_kernel(const __nv_bfloat16* __restrict__ qkv,
                            const float* __restrict__ tau,
                            __nv_bfloat16* __restrict__ att) {
    __shared__ float qs[16][68], ks[16][68], vs[16][68];
    __shared__ float rq[16], rk[16];
    __shared__ float at[16][17];
    __shared__ float tauv;

    int n = blockIdx.x, hh = blockIdx.y, b = blockIdx.z;
    int tid = threadIdx.x;                  // 256

    {
        int rr  = tid >> 4;
        int c4 = (tid & 15) << 2;
        int t  = n*WSZ + rr;
        float4 q4 = make_float4(0.f,0.f,0.f,0.f), k4 = q4, v4 = q4;
        if (t < TLEN) {
            size_t bb = (size_t)(b*TLEN + t) * (3*CH) + hh*HDIM + c4;
            uint2 qu = *reinterpret_cast<const uint2*>(qkv + bb);
            uint2 ku = *reinterpret_cast<const uint2*>(qkv + bb + CH);
            uint2 vu = *reinterpret_cast<const uint2*>(qkv + bb + 2*CH);
            float2 a0 = __bfloat1622float2(*reinterpret_cast<__nv_bfloat162*>(&qu.x));
            float2 a1 = __bfloat1622float2(*reinterpret_cast<__nv_bfloat162*>(&qu.y));
            q4 = make_float4(a0.x, a0.y, a1.x, a1.y);
            a0 = __bfloat1622float2(*reinterpret_cast<__nv_bfloat162*>(&ku.x));
            a1 = __bfloat1622float2(*reinterpret_cast<__nv_bfloat162*>(&ku.y));
            k4 = make_float4(a0.x, a0.y, a1.x, a1.y);
            a0 = __bfloat1622float2(*reinterpret_cast<__nv_bfloat162*>(&vu.x));
            a1 = __bfloat1622float2(*reinterpret_cast<__nv_bfloat162*>(&vu.y));
            v4 = make_float4(a0.x, a0.y, a1.x, a1.y);
        }
        *reinterpret_cast<float4*>(&qs[rr][c4]) = q4;
        *reinterpret_cast<float4*>(&ks[rr][c4]) = k4;
        *reinterpret_cast<float4*>(&vs[rr][c4]) = v4;
        if (tid == 0) tauv = tau[hh] + 1e-6f;
    }
    __syncthreads();

    if (tid < 32) {
        const float* p = (tid < 16) ? &qs[tid][0] : &ks[tid-16][0];
        float ssum = 0.f;
        #pragma unroll
        for (int i = 0; i < 64; i++) ssum += p[i]*p[i];
        float inv = 1.0f / fmaxf(sqrtf(ssum), 1e-12f);
        if (tid < 16) rq[tid] = inv; else rk[tid-16] = inv;
    }
    __syncthreads();

    int w  = tid >> 4;
    int s2 = tid & 15;
    float dot = 0.f;
    #pragma unroll
    for (int i = 0; i < 64; i++) dot += qs[w][i] * ks[s2][i];
    float logit = dot * rq[w] * rk[s2] / tauv;

    float mx = logit;
    #pragma unroll
    for (int m = 8; m; m >>= 1) mx = fmaxf(mx, __shfl_xor_sync(0xffffffffu, mx, m));
    float e = expf(logit - mx);
    float ssum = e;
    #pragma unroll
    for (int m = 8; m; m >>= 1) ssum += __shfl_xor_sync(0xffffffffu, ssum, m);
    at[w][s2] = e / ssum;
    __syncthreads();

    int c0 = (tid & 15) << 2;
    float o0=0.f, o1=0.f, o2=0.f, o3=0.f;
    #pragma unroll
    for (int ss = 0; ss < 16; ss++) {
        float a = at[w][ss];
        o0 += a * vs[ss][c0+0];
        o1 += a * vs[ss][c0+1];
        o2 += a * vs[ss][c0+2];
        o3 += a * vs[ss][c0+3];
    }
    int t = n*WSZ + w;
    if (t < TLEN) {
        __nv_bfloat16* dst = att + (size_t)(b*TLEN + t)*CH + hh*HDIM + c0;
        *reinterpret_cast<__nv_bfloat162*>(dst)     = __floats2bfloat162_rn(o0, o1);
        *reinterpret_cast<__nv_bfloat162*>(dst + 2) = __floats2bfloat162_rn(o2, o3);
    }
}

// ---------------------------------------------------------------------------
// K8: y = x + o*0.5 broadcast. Pointers pre-offset to chunk (2 batches).
// ---------------------------------------------------------------------------
__global__ void final_kernel(const float* __restrict__ x, const float* __restrict__ o,
                             float* __restrict__ y) {
    unsigned i4 = blockIdx.x * 256u + threadIdx.x;    // over 2*CH*TLEN*16 float4
    if (i4 >= (unsigned)(2*CH*TLEN*16)) return;
    unsigned row = i4 >> 4;              // (b_local, c, t)
    unsigned t  = row % TLEN;
    unsigned bc = row / TLEN;
    unsigned c  = bc % CH;
    unsigned b  = bc / CH;               // 0..1
    float val = __ldg(o + (size_t)(b*TLEN + t)*CH + c) * 0.5f;
    float4 xv = reinterpret_cast<const float4*>(x)[i4];
    xv.x += val; xv.y += val; xv.z += val; xv.w += val;
    reinterpret_cast<float4*>(y)[i4] = xv;
}

// ---------------------------------------------------------------------------
// Launch: two token-chunk pipelines on two streams, chunk B STAGGERED by
// chunk A's meanln so DRAM-bound and tensor-bound phases interleave.
// ---------------------------------------------------------------------------
extern "C" void kernel_launch(void* const* d_in, const int* in_sizes, int n_in,
                              void* d_out, int out_size) {
    const float* x      = (const float*)d_in[0];
    const float* ln_g   = (const float*)d_in[1];
    const float* ln_b   = (const float*)d_in[2];
    const float* tau    = (const float*)d_in[3];
    const float* w_qkv  = (const float*)d_in[4];
    const float* b_qkv  = (const float*)d_in[5];
    const float* w_proj = (const float*)d_in[6];
    const float* b_proj = (const float*)d_in[7];
    const float* w_mlp1 = (const float*)d_in[8];
    const float* b_mlp1 = (const float*)d_in[9];
    const float* w_mlp2 = (const float*)d_in[10];
    const float* b_mlp2 = (const float*)d_in[11];
    float* y = (float*)d_out;

    float *y0, *o, *part;
    __nv_bfloat16 *snh, *qkvh, *atth, *y0h, *mlph, *wqkvT, *wprojT, *wmlp1T, *wmlp2T;
    cudaGetSymbolAddress((void**)&snh,    g_snh);
    cudaGetSymbolAddress((void**)&qkvh,   g_qkvh);
    cudaGetSymbolAddress((void**)&atth,   g_atth);
    cudaGetSymbolAddress((void**)&y0,     g_y0);
    cudaGetSymbolAddress((void**)&y0h,    g_y0h);
    cudaGetSymbolAddress((void**)&mlph,   g_mlph);
    cudaGetSymbolAddress((void**)&o,      g_o);
    cudaGetSymbolAddress((void**)&part,   g_part);
    cudaGetSymbolAddress((void**)&wqkvT,  g_wqkvT);
    cudaGetSymbolAddress((void**)&wprojT, g_wprojT);
    cudaGetSymbolAddress((void**)&wmlp1T, g_wmlp1T);
    cudaGetSymbolAddress((void**)&wmlp2T, g_wmlp2T);

    cudaFuncSetAttribute(gemm_bf16<4,1>, cudaFuncAttributeMaxDynamicSharedMemorySize, GS_TOTAL);
    cudaFuncSetAttribute(gemm_bf16<1,1>, cudaFuncAttributeMaxDynamicSharedMemorySize, GS_TOTAL);
    cudaFuncSetAttribute(gemm_bf16<5,2>, cudaFuncAttributeMaxDynamicSharedMemorySize, GS_TOTAL);
    cudaFuncSetAttribute(gemm_bf16<5,4>, cudaFuncAttributeMaxDynamicSharedMemorySize, GS_TOTAL);

    static cudaStream_t sA = nullptr, sB = nullptr, sW = nullptr;
    static cudaEvent_t  e0 = nullptr, eW = nullptr, eA = nullptr, eB = nullptr, eM = nullptr;
    if (!sA) {
        cudaStreamCreateWithFlags(&sA, cudaStreamNonBlocking);
        cudaStreamCreateWithFlags(&sB, cudaStreamNonBlocking);
        cudaStreamCreateWithFlags(&sW, cudaStreamNonBlocking);
        cudaEventCreateWithFlags(&e0, cudaEventDisableTiming);
        cudaEventCreateWithFlags(&eW, cudaEventDisableTiming);
        cudaEventCreateWithFlags(&eA, cudaEventDisableTiming);
        cudaEventCreateWithFlags(&eB, cudaEventDisableTiming);
        cudaEventCreateWithFlags(&eM, cudaEventDisableTiming);
    }

    // fork
    cudaEventRecord(e0, 0);
    cudaStreamWaitEvent(sA, e0, 0);
    cudaStreamWaitEvent(sB, e0, 0);
    cudaStreamWaitEvent(sW, e0, 0);

    // weight conversions on sW
    wconv_kernel<<<dim3(3*CH/32, CH/64),  dim3(32,8), 0, sW>>>(w_qkv,  wqkvT,  CH,   3*CH);
    wconv_kernel<<<dim3(CH/32,   CH/64),  dim3(32,8), 0, sW>>>(w_proj, wprojT, CH,   CH);
    wconv_kernel<<<dim3(MLPC/32, CH/64),  dim3(32,8), 0, sW>>>(w_mlp1, wmlp1T, CH,   MLPC);
    wconv_kernel<<<dim3(CH/32,   MLPC/64),dim3(32,8), 0, sW>>>(w_mlp2, wmlp2T, MLPC, CH);
    cudaEventRecord(eW, sW);

    cudaStream_t cs[2] = {sA, sB};
    for (int ck = 0; ck < 2; ck++) {
        cudaStream_t st = cs[ck];
        const size_t to  = (size_t)ck * CTOK;          // token offset
        __nv_bfloat16* snh_c  = snh  + to * CH;
        __nv_bfloat16* qkv_c  = qkvh + to * 3*CH;
        __nv_bfloat16* att_c  = atth + to * CH;
        float*         y0_c   = y0   + to * CH;
        __nv_bfloat16* y0h_c  = y0h  + to * CH;
        __nv_bfloat16* mlp_c  = mlph + to * MLPC;
        float*         o_c    = o    + to * CH;
        float*         part_c = part + (size_t)ck * 4 * CTOK * CH;
        const float*   x_c    = x + (size_t)ck * 2 * CH * TLEN * 64;
        float*         y_c    = y + (size_t)ck * 2 * CH * TLEN * 64;

        // stagger: chunk B's meanln starts only after chunk A's meanln done,
        // so B's DRAM phase overlaps A's tensor phase (and shifted so on).
        if (ck == 1) cudaStreamWaitEvent(st, eM, 0);

        meanln_kernel<<<CTOK, 256, 0, st>>>(x, ln_g, ln_b, snh, ck * 2);
        if (ck == 0) cudaEventRecord(eM, sA);

        cudaStreamWaitEvent(st, eW, 0);

        // qkv: 2000 x 2304
        gemm_bf16<4,1><<<dim3(3*CH/128, 16), 256, GS_TOTAL, st>>>(
            snh_c, wqkvT, b_qkv, nullptr, qkv_c, CTOK, 3*CH, CH);
        attn_kernel<<<dim3(NWIN, HEADS, 2), 256, 0, st>>>(qkv_c, tau, att_c);

        // proj: 2000 x 768, split-K 2
        gemm_bf16<5,2><<<dim3(CH/128, 16, 2), 256, GS_TOTAL, st>>>(
            att_c, wprojT, nullptr, part_c, nullptr, CTOK, CH, CH);
        reduce_proj_kernel<<<(CTOK*CH/4 + 255)/256, 256, 0, st>>>(part_c, b_proj, y0_c, y0h_c);

        // mlp1 + gelu: 2000 x 3072
        gemm_bf16<1,1><<<dim3(MLPC/128, 16), 256, GS_TOTAL, st>>>(
            y0h_c, wmlp1T, b_mlp1, nullptr, mlp_c, CTOK, MLPC, CH);
        // mlp2: 2000 x 768, split-K 4
        gemm_bf16<5,4><<<dim3(CH/128, 16, 4), 256, GS_TOTAL, st>>>(
            mlp_c, wmlp2T, nullptr, part_c, nullptr, CTOK, CH, MLPC);
        reduce_mlp2_kernel<<<(CTOK*CH/4 + 255)/256, 256, 0, st>>>(part_c, b_mlp2, y0_c, o_c);

        final_kernel<<<(2*CH*TLEN*16 + 255)/256, 256, 0, st>>>(x_c, o_c, y_c);
    }

    // join
    cudaEventRecord(eA, sA);
    cudaEventRecord(eB, sB);
    cudaStreamWaitEvent(0, eA, 0);
    cudaStreamWaitEvent(0, eB, 0);
}

// round 17
// speedup vs baseline: 1.1225x; 1.0833x over previous
#include <cuda_runtime.h>
#include <cuda_bf16.h>
#include <cstdint>

// ---------------------------------------------------------------------------
// Problem constants
// ---------------------------------------------------------------------------
#define BATCH 4
#define CH    768
#define TLEN  1000
#define HEADS 12
#define HDIM  64
#define WSZ   16
#define NWIN  63
#define NTOK  (BATCH*TLEN)       // 4000
#define MLPC  (4*CH)             // 3072
#define CTOK  2000               // tokens per chunk (2 batches)

// ---------------------------------------------------------------------------
// Scratch (device globals; allocation-free)
// ---------------------------------------------------------------------------
__device__ __nv_bfloat16  g_snh [NTOK*CH];
__device__ __nv_bfloat16  g_qkvh[NTOK*3*CH];
__device__ __nv_bfloat16  g_atth[NTOK*CH];
__device__ float          g_y0  [NTOK*CH];
__device__ __nv_bfloat16  g_y0h [NTOK*CH];
__device__ __nv_bfloat16  g_mlph[NTOK*MLPC];
__device__ float          g_o   [NTOK*CH];
__device__ float          g_part[4*NTOK*CH];      // [chunk][4][CTOK][CH]
__device__ __nv_bfloat16  g_wqkvT [3*CH*CH];
__device__ __nv_bfloat16  g_wprojT[CH*CH];
__device__ __nv_bfloat16  g_wmlp1T[MLPC*CH];
__device__ __nv_bfloat16  g_wmlp2T[CH*MLPC];

// ---------------------------------------------------------------------------
// Helpers
// ---------------------------------------------------------------------------
__device__ __forceinline__ uint32_t smem_u32(const void* p) {
    uint32_t a;
    asm("{ .reg .u64 t; cvta.to.shared.u64 t, %1; cvt.u32.u64 %0, t; }" : "=r"(a) : "l"(p));
    return a;
}

__device__ __forceinline__ void mma_bf16(float* c, const uint32_t* a, const uint32_t* b) {
    asm volatile(
        "mma.sync.aligned.m16n8k16.row.col.f32.bf16.bf16.f32 "
        "{%0,%1,%2,%3},{%4,%5,%6,%7},{%8,%9},{%0,%1,%2,%3};"
        : "+f"(c[0]), "+f"(c[1]), "+f"(c[2]), "+f"(c[3])
        : "r"(a[0]), "r"(a[1]), "r"(a[2]), "r"(a[3]), "r"(b[0]), "r"(b[1]));
}

__device__ __forceinline__ void cp_async16_sh(uint32_t dst, const void* src, int n) {
    asm volatile("cp.async.cg.shared.global [%0], [%1], 16, %2;"
                 :: "r"(dst), "l"(src), "r"(n));
}

#define LDSM_X4(r0, r1, r2, r3, addr)                                         \
    asm volatile("ldmatrix.sync.aligned.m8n8.x4.shared.b16 {%0,%1,%2,%3}, [%4];" \
                 : "=r"(r0), "=r"(r1), "=r"(r2), "=r"(r3) : "r"(addr))

// ---------------------------------------------------------------------------
// K1: fused spatial mean + LayerNorm, COALESCED.
// One block per token. Each 16-lane group reads one full contiguous 256B
// c-row (16 consecutive float4s) -> 100% sector efficiency. Spatial means
// land in smem; LN reduction runs over smem.
// ---------------------------------------------------------------------------
__global__ __launch_bounds__(256)
void meanln_kernel(const float* __restrict__ x, const float* __restrict__ gg,
                   const float* __restrict__ bb, __nv_bfloat16* __restrict__ sn,
                   int b0) {
    __shared__ float sc[CH];
    __shared__ float red[2][8];
    int tokl = blockIdx.x;             // 0..CTOK-1
    int b    = b0 + tokl / TLEN;
    int t    = tokl % TLEN;
    int tid  = threadIdx.x;            // 256
    int grp  = tid >> 4;               // 0..15: c-row group
    int l16  = tid & 15;

    const float* xb = x + ((size_t)b * CH * TLEN + t) * 64;
    #pragma unroll 4
    for (int it = 0; it < CH/16; it++) {         // 48 iterations
        int c = it * 16 + grp;
        const float4* p = reinterpret_cast<const float4*>(xb + (size_t)c * TLEN * 64);
        float4 v = p[l16];
        float s = (v.x + v.y) + (v.z + v.w);
        s += __shfl_xor_sync(0xffffffffu, s, 1);
        s += __shfl_xor_sync(0xffffffffu, s, 2);
        s += __shfl_xor_sync(0xffffffffu, s, 4);
        s += __shfl_xor_sync(0xffffffffu, s, 8);
        if (l16 == 0) sc[c] = s * (1.0f/64.0f);
    }
    __syncthreads();

    float v0 = sc[tid], v1 = sc[tid+256], v2 = sc[tid+512];
    float sum = v0+v1+v2;
    float sq  = v0*v0 + v1*v1 + v2*v2;
    #pragma unroll
    for (int m = 16; m; m >>= 1) {
        sum += __shfl_xor_sync(0xffffffffu, sum, m);
        sq  += __shfl_xor_sync(0xffffffffu, sq,  m);
    }
    if ((tid & 31) == 0) { red[0][tid>>5] = sum; red[1][tid>>5] = sq; }
    __syncthreads();
    if (tid < 32) {
        float a  = (tid < 8) ? red[0][tid] : 0.f;
        float b2 = (tid < 8) ? red[1][tid] : 0.f;
        #pragma unroll
        for (int m = 4; m; m >>= 1) {
            a  += __shfl_xor_sync(0xffffffffu, a,  m);
            b2 += __shfl_xor_sync(0xffffffffu, b2, m);
        }
        if (tid == 0) { red[0][0] = a; red[1][0] = b2; }
    }
    __syncthreads();
    float mean = red[0][0] * (1.0f/768.0f);
    float var  = red[1][0] * (1.0f/768.0f) - mean*mean;
    float rstd = rsqrtf(var + 1e-5f);
    __nv_bfloat16* orow = sn + ((size_t)b * TLEN + t) * CH;
    orow[tid    ] = __float2bfloat16((v0-mean)*rstd*gg[tid    ] + bb[tid    ]);
    orow[tid+256] = __float2bfloat16((v1-mean)*rstd*gg[tid+256] + bb[tid+256]);
    orow[tid+512] = __float2bfloat16((v2-mean)*rstd*gg[tid+512] + bb[tid+512]);
}

// ---------------------------------------------------------------------------
// K3: weight convert + transpose.  W fp32 [K][N] -> WT bf16 [N][K]
// ---------------------------------------------------------------------------
__global__ void wconv_kernel(const float* __restrict__ W, __nv_bfloat16* __restrict__ WT,
                             int K, int N) {
    __shared__ float t[64][33];
    int bx = blockIdx.x * 32;   // n base
    int by = blockIdx.y * 64;   // k base
    int tx = threadIdx.x, ty = threadIdx.y;    // 32 x 8
    #pragma unroll
    for (int i = ty; i < 64; i += 8)
        t[i][tx] = W[(size_t)(by + i) * N + bx + tx];
    __syncthreads();
    #pragma unroll
    for (int i = ty; i < 32; i += 8) {
        __nv_bfloat162 h = __floats2bfloat162_rn(t[2*tx][i], t[2*tx+1][i]);
        *reinterpret_cast<__nv_bfloat162*>(WT + (size_t)(bx + i) * K + by + 2*tx) = h;
    }
}

// ---------------------------------------------------------------------------
// GEMM: C = A(MxK,bf16 row-major) @ BT(NxK,bf16 K-major)^T
// bf16 mma.sync m16n8k16, block 128x128x64, 8 warps (2x4), warp tile 64x32.
// 2-stage cp.async, 1 barrier per 64-K slice, ldmatrix.x4 (72-half stride).
// EPI: 1 = bias + exact GELU -> bf16 Ch
//      4 = bias -> bf16 Ch
//      5 = raw partial (no bias) -> fp32 C at split offset (blockIdx.z)
// ---------------------------------------------------------------------------
#define GS_OPER   18432u
#define GS_STAGE  36864u
#define GS_TOTAL  73728

template<int EPI, int SPLIT>
__global__ __launch_bounds__(256, 2)
void gemm_bf16(const __nv_bfloat16* __restrict__ A, const __nv_bfloat16* __restrict__ BT,
               const float* __restrict__ bias,
               float* __restrict__ C, __nv_bfloat16* __restrict__ Ch,
               int M, int N, int K)
{
    extern __shared__ __nv_bfloat16 smem[];
    const uint32_t smemu = smem_u32(smem);

    int tid  = threadIdx.x;
    int lane = tid & 31, warp = tid >> 5;
    int wm = warp >> 2, wn = warp & 3;
    int bm = blockIdx.y * 128, bn = blockIdx.x * 128;
    int g  = lane >> 2, tg = lane & 3;

    const int KTtot = K >> 6;
    const int per   = KTtot / SPLIT;
    const int kz    = (SPLIT > 1) ? blockIdx.z : 0;
    const int kt0   = kz * per;
    const int kt1   = kt0 + per;

    int crow  = tid >> 1;
    int coffh = (tid & 1) * 32;
    int arow = bm + crow; if (arow > M-1) arow = M-1;
    int aok  = (bm + crow < M) ? 16 : 0;
    const __nv_bfloat16* gA = A  + (size_t)arow      * K + coffh;
    const __nv_bfloat16* gB = BT + (size_t)(bn+crow) * K + coffh;
    const uint32_t dstOff = (uint32_t)crow * 144u + (uint32_t)coffh * 2u;

    const uint32_t aFrag = (uint32_t)(wm*64 + (lane & 7) + ((lane >> 3) & 1) * 8) * 144u
                         + (uint32_t)((lane >> 4) * 8) * 2u;
    const uint32_t bFrag = (uint32_t)(wn*32 + (lane & 7) + ((lane >> 4) & 1) * 8) * 144u
                         + (uint32_t)(((lane >> 3) & 1) * 8) * 2u;

    float acc[4][4][4];
    #pragma unroll
    for (int i = 0; i < 4; i++)
        #pragma unroll
        for (int j = 0; j < 4; j++)
            #pragma unroll
            for (int r = 0; r < 4; r++) acc[i][j][r] = 0.f;

    auto prefetch = [&](int c) {
        uint32_t da = smemu + (uint32_t)(c & 1) * GS_STAGE + dstOff;
        uint32_t db = da + GS_OPER;
        const __nv_bfloat16* sa = gA + c * 64;
        const __nv_bfloat16* sb = gB + c * 64;
        #pragma unroll
        for (int j = 0; j < 4; j++) {
            cp_async16_sh(da + j*16u, sa + j*8, aok);
            cp_async16_sh(db + j*16u, sb + j*8, 16);
        }
        asm volatile("cp.async.commit_group;");
    };

    prefetch(kt0);

    for (int kt = kt0; kt < kt1; kt++) {
        asm volatile("cp.async.wait_group 0;");
        __syncthreads();
        if (kt + 1 < kt1) prefetch(kt + 1);

        uint32_t aB = smemu + (uint32_t)(kt & 1) * GS_STAGE + aFrag;
        uint32_t bB = aB - aFrag + GS_OPER + bFrag;
        #pragma unroll
        for (int kk = 0; kk < 4; kk++) {
            uint32_t kby = (uint32_t)kk * 32u;
            uint32_t af[4][4], bf[4][2];
            #pragma unroll
            for (int mi = 0; mi < 4; mi++)
                LDSM_X4(af[mi][0], af[mi][1], af[mi][2], af[mi][3],
                        aB + (uint32_t)mi * (16u*144u) + kby);
            #pragma unroll
            for (int p = 0; p < 2; p++)
                LDSM_X4(bf[2*p][0], bf[2*p][1], bf[2*p+1][0], bf[2*p+1][1],
                        bB + (uint32_t)p * (16u*144u) + kby);
            #pragma unroll
            for (int mi = 0; mi < 4; mi++)
                #pragma unroll
                for (int ni = 0; ni < 4; ni++)
                    mma_bf16(acc[mi][ni], af[mi], bf[ni]);
        }
    }

    // ---- epilogue ----
    float* Cpart = (EPI == 5) ? (C + (size_t)kz * M * N) : C;
    #pragma unroll
    for (int mi = 0; mi < 4; mi++) {
        int r0 = bm + wm*64 + mi*16 + g;
        #pragma unroll
        for (int ni = 0; ni < 4; ni++) {
            int c0 = bn + wn*32 + ni*8 + 2*tg;
            float b0 = 0.f, b1 = 0.f;
            if (EPI != 5) { b0 = bias[c0]; b1 = bias[c0+1]; }
            #pragma unroll
            for (int half = 0; half < 2; half++) {
                int r = r0 + half*8;
                if (r < M) {
                    float v0 = acc[mi][ni][half*2]   + b0;
                    float v1 = acc[mi][ni][half*2+1] + b1;
                    if (EPI == 1) { v0 = v0 * normcdff(v0); v1 = v1 * normcdff(v1); }
                    if (EPI == 5)
                        *reinterpret_cast<float2*>(Cpart + (size_t)r*N + c0) = make_float2(v0, v1);
                    else
                        *reinterpret_cast<__nv_bfloat162*>(Ch + (size_t)r*N + c0) =
                            __floats2bfloat162_rn(v0, v1);
                }
            }
        }
    }
}

// ---------------------------------------------------------------------------
// Split-K reduce kernels (fixed-order sums -> deterministic). Per chunk.
// ---------------------------------------------------------------------------
__global__ void reduce_proj_kernel(const float* __restrict__ part,
                                   const float* __restrict__ bias,
                                   float* __restrict__ y0, __nv_bfloat16* __restrict__ y0h) {
    unsigned i = blockIdx.x * 256u + threadIdx.x;       // over CTOK*CH/4
    if (i >= (unsigned)(CTOK*CH/4)) return;
    const float4 p0 = reinterpret_cast<const float4*>(part)[i];
    const float4 p1 = reinterpret_cast<const float4*>(part + (size_t)CTOK*CH)[i];
    const float4 bv = reinterpret_cast<const float4*>(bias)[i % (CH/4)];
    float4 v;
    v.x = p0.x + p1.x + bv.x;
    v.y = p0.y + p1.y + bv.y;
    v.z = p0.z + p1.z + bv.z;
    v.w = p0.w + p1.w + bv.w;
    reinterpret_cast<float4*>(y0)[i] = v;
    reinterpret_cast<__nv_bfloat162*>(y0h)[2*i]   = __floats2bfloat162_rn(v.x, v.y);
    reinterpret_cast<__nv_bfloat162*>(y0h)[2*i+1] = __floats2bfloat162_rn(v.z, v.w);
}

__global__ void reduce_mlp2_kernel(const float* __restrict__ part,
                                   const float* __restrict__ bias,
                                   const float* __restrict__ y0,
                                   float* __restrict__ o) {
    unsigned i = blockIdx.x * 256u + threadIdx.x;       // over CTOK*CH/4
    if (i >= (unsigned)(CTOK*CH/4)) return;
    const size_t str = (size_t)CTOK*CH;
    const float4 p0 = reinterpret_cast<const float4*>(part)[i];
    const float4 p1 = reinterpret_cast<const float4*>(part + str)[i];
    const float4 p2 = reinterpret_cast<const float4*>(part + 2*str)[i];
    const float4 p3 = reinterpret_cast<const float4*>(part + 3*str)[i];
    const float4 bv = reinterpret_cast<const float4*>(bias)[i % (CH/4)];
    const float4 rv = reinterpret_cast<const float4*>(y0)[i];
    float4 v;
    v.x = ((p0.x + p1.x) + (p2.x + p3.x)) + bv.x + rv.x;
    v.y = ((p0.y + p1.y) + (p2.y + p3.y)) + bv.y + rv.y;
    v.z = ((p0.z + p1.z) + (p2.z + p3.z)) + bv.z + rv.z;
    v.w = ((p0.w + p1.w) + (p2.w + p3.w)) + bv.w + rv.w;
    reinterpret_cast<float4*>(o)[i] = v;
}

// ---------------------------------------------------------------------------
// K4: windowed cosine attention (bf16 in, bf16 out). Pointers pre-offset
// to chunk; blockIdx.z = local batch.
// ---------------------------------------------------------------------------
__global__ void attn_kernel(const __nv_bfloat16* __restrict__ qkv,
                            const float* __restrict__ tau,
                            __nv_bfloat16* __restrict__ att) {
    __shared__ float qs[16][68], ks[16][68], vs[16][68];
    __shared__ float rq[16], rk[16];
    __shared__ float at[16][17];
    __shared__ float tauv;

    int n = blockIdx.x, hh = blockIdx.y, b = blockIdx.z;
    int tid = threadIdx.x;                  // 256

    {
        int rr  = tid >> 4;
        int c4 = (tid & 15) << 2;
        int t  = n*WSZ + rr;
        float4 q4 = make_float4(0.f,0.f,0.f,0.f), k4 = q4, v4 = q4;
        if (t < TLEN) {
            size_t bb = (size_t)(b*TLEN + t) * (3*CH) + hh*HDIM + c4;
            uint2 qu = *reinterpret_cast<const uint2*>(qkv + bb);
            uint2 ku = *reinterpret_cast<const uint2*>(qkv + bb + CH);
            uint2 vu = *reinterpret_cast<const uint2*>(qkv + bb + 2*CH);
            float2 a0 = __bfloat1622float2(*reinterpret_cast<__nv_bfloat162*>(&qu.x));
            float2 a1 = __bfloat1622float2(*reinterpret_cast<__nv_bfloat162*>(&qu.y));
            q4 = make_float4(a0.x, a0.y, a1.x, a1.y);
            a0 = __bfloat1622float2(*reinterpret_cast<__nv_bfloat162*>(&ku.x));
            a1 = __bfloat1622float2(*reinterpret_cast<__nv_bfloat162*>(&ku.y));
            k4 = make_float4(a0.x, a0.y, a1.x, a1.y);
            a0 = __bfloat1622float2(*reinterpret_cast<__nv_bfloat162*>(&vu.x));
            a1 = __bfloat1622float2(*reinterpret_cast<__nv_bfloat162*>(&vu.y));
            v4 = make_float4(a0.x, a0.y, a1.x, a1.y);
        }
        *reinterpret_cast<float4*>(&qs[rr][c4]) = q4;
        *reinterpret_cast<float4*>(&ks[rr][c4]) = k4;
        *reinterpret_cast<float4*>(&vs[rr][c4]) = v4;
        if (tid == 0) tauv = tau[hh] + 1e-6f;
    }
    __syncthreads();

    if (tid < 32) {
        const float* p = (tid < 16) ? &qs[tid][0] : &ks[tid-16][0];
        float ssum = 0.f;
        #pragma unroll
        for (int i = 0; i < 64; i++) ssum += p[i]*p[i];
        float inv = 1.0f / fmaxf(sqrtf(ssum), 1e-12f);
        if (tid < 16) rq[tid] = inv; else rk[tid-16] = inv;
    }
    __syncthreads();

    int w  = tid >> 4;
    int s2 = tid & 15;
    float dot = 0.f;
    #pragma unroll
    for (int i = 0; i < 64; i++) dot += qs[w][i] * ks[s2][i];
    float logit = dot * rq[w] * rk[s2] / tauv;

    float mx = logit;
    #pragma unroll
    for (int m = 8; m; m >>= 1) mx = fmaxf(mx, __shfl_xor_sync(0xffffffffu, mx, m));
    float e = expf(logit - mx);
    float ssum = e;
    #pragma unroll
    for (int m = 8; m; m >>= 1) ssum += __shfl_xor_sync(0xffffffffu, ssum, m);
    at[w][s2] = e / ssum;
    __syncthreads();

    int c0 = (tid & 15) << 2;
    float o0=0.f, o1=0.f, o2=0.f, o3=0.f;
    #pragma unroll
    for (int ss = 0; ss < 16; ss++) {
        float a = at[w][ss];
        o0 += a * vs[ss][c0+0];
        o1 += a * vs[ss][c0+1];
        o2 += a * vs[ss][c0+2];
        o3 += a * vs[ss][c0+3];
    }
    int t = n*WSZ + w;
    if (t < TLEN) {
        __nv_bfloat16* dst = att + (size_t)(b*TLEN + t)*CH + hh*HDIM + c0;
        *reinterpret_cast<__nv_bfloat162*>(dst)     = __floats2bfloat162_rn(o0, o1);
        *reinterpret_cast<__nv_bfloat162*>(dst + 2) = __floats2bfloat162_rn(o2, o3);
    }
}

// ---------------------------------------------------------------------------
// K8: y = x + o*0.5 broadcast. Pointers pre-offset to chunk (2 batches).
// ---------------------------------------------------------------------------
__global__ void final_kernel(const float* __restrict__ x, const float* __restrict__ o,
                             float* __restrict__ y) {
    unsigned i4 = blockIdx.x * 256u + threadIdx.x;    // over 2*CH*TLEN*16 float4
    if (i4 >= (unsigned)(2*CH*TLEN*16)) return;
    unsigned row = i4 >> 4;              // (b_local, c, t)
    unsigned t  = row % TLEN;
    unsigned bc = row / TLEN;
    unsigned c  = bc % CH;
    unsigned b  = bc / CH;               // 0..1
    float val = __ldg(o + (size_t)(b*TLEN + t)*CH + c) * 0.5f;
    float4 xv = reinterpret_cast<const float4*>(x)[i4];
    xv.x += val; xv.y += val; xv.z += val; xv.w += val;
    reinterpret_cast<float4*>(y)[i4] = xv;
}

// ---------------------------------------------------------------------------
// Launch: two independent token-chunk pipelines on two streams (R11 topology).
// ---------------------------------------------------------------------------
extern "C" void kernel_launch(void* const* d_in, const int* in_sizes, int n_in,
                              void* d_out, int out_size) {
    const float* x      = (const float*)d_in[0];
    const float* ln_g   = (const float*)d_in[1];
    const float* ln_b   = (const float*)d_in[2];
    const float* tau    = (const float*)d_in[3];
    const float* w_qkv  = (const float*)d_in[4];
    const float* b_qkv  = (const float*)d_in[5];
    const float* w_proj = (const float*)d_in[6];
    const float* b_proj = (const float*)d_in[7];
    const float* w_mlp1 = (const float*)d_in[8];
    const float* b_mlp1 = (const float*)d_in[9];
    const float* w_mlp2 = (const float*)d_in[10];
    const float* b_mlp2 = (const float*)d_in[11];
    float* y = (float*)d_out;

    float *y0, *o, *part;
    __nv_bfloat16 *snh, *qkvh, *atth, *y0h, *mlph, *wqkvT, *wprojT, *wmlp1T, *wmlp2T;
    cudaGetSymbolAddress((void**)&snh,    g_snh);
    cudaGetSymbolAddress((void**)&qkvh,   g_qkvh);
    cudaGetSymbolAddress((void**)&atth,   g_atth);
    cudaGetSymbolAddress((void**)&y0,     g_y0);
    cudaGetSymbolAddress((void**)&y0h,    g_y0h);
    cudaGetSymbolAddress((void**)&mlph,   g_mlph);
    cudaGetSymbolAddress((void**)&o,      g_o);
    cudaGetSymbolAddress((void**)&part,   g_part);
    cudaGetSymbolAddress((void**)&wqkvT,  g_wqkvT);
    cudaGetSymbolAddress((void**)&wprojT, g_wprojT);
    cudaGetSymbolAddress((void**)&wmlp1T, g_wmlp1T);
    cudaGetSymbolAddress((void**)&wmlp2T, g_wmlp2T);

    cudaFuncSetAttribute(gemm_bf16<4,1>, cudaFuncAttributeMaxDynamicSharedMemorySize, GS_TOTAL);
    cudaFuncSetAttribute(gemm_bf16<1,1>, cudaFuncAttributeMaxDynamicSharedMemorySize, GS_TOTAL);
    cudaFuncSetAttribute(gemm_bf16<5,2>, cudaFuncAttributeMaxDynamicSharedMemorySize, GS_TOTAL);
    cudaFuncSetAttribute(gemm_bf16<5,4>, cudaFuncAttributeMaxDynamicSharedMemorySize, GS_TOTAL);

    static cudaStream_t sA = nullptr, sB = nullptr, sW = nullptr;
    static cudaEvent_t  e0 = nullptr, eW = nullptr, eA = nullptr, eB = nullptr;
    if (!sA) {
        cudaStreamCreateWithFlags(&sA, cudaStreamNonBlocking);
        cudaStreamCreateWithFlags(&sB, cudaStreamNonBlocking);
        cudaStreamCreateWithFlags(&sW, cudaStreamNonBlocking);
        cudaEventCreateWithFlags(&e0, cudaEventDisableTiming);
        cudaEventCreateWithFlags(&eW, cudaEventDisableTiming);
        cudaEventCreateWithFlags(&eA, cudaEventDisableTiming);
        cudaEventCreateWithFlags(&eB, cudaEventDisableTiming);
    }

    // fork
    cudaEventRecord(e0, 0);
    cudaStreamWaitEvent(sA, e0, 0);
    cudaStreamWaitEvent(sB, e0, 0);
    cudaStreamWaitEvent(sW, e0, 0);

    // weight conversions on sW
    wconv_kernel<<<dim3(3*CH/32, CH/64),  dim3(32,8), 0, sW>>>(w_qkv,  wqkvT,  CH,   3*CH);
    wconv_kernel<<<dim3(CH/32,   CH/64),  dim3(32,8), 0, sW>>>(w_proj, wprojT, CH,   CH);
    wconv_kernel<<<dim3(MLPC/32, CH/64),  dim3(32,8), 0, sW>>>(w_mlp1, wmlp1T, CH,   MLPC);
    wconv_kernel<<<dim3(CH/32,   MLPC/64),dim3(32,8), 0, sW>>>(w_mlp2, wmlp2T, MLPC, CH);
    cudaEventRecord(eW, sW);

    cudaStream_t cs[2] = {sA, sB};
    for (int ck = 0; ck < 2; ck++) {
        cudaStream_t st = cs[ck];
        const size_t to  = (size_t)ck * CTOK;          // token offset
        __nv_bfloat16* snh_c  = snh  + to * CH;
        __nv_bfloat16* qkv_c  = qkvh + to * 3*CH;
        __nv_bfloat16* att_c  = atth + to * CH;
        float*         y0_c   = y0   + to * CH;
        __nv_bfloat16* y0h_c  = y0h  + to * CH;
        __nv_bfloat16* mlp_c  = mlph + to * MLPC;
        float*         o_c    = o    + to * CH;
        float*         part_c = part + (size_t)ck * 4 * CTOK * CH;
        const float*   x_c    = x + (size_t)ck * 2 * CH * TLEN * 64;
        float*         y_c    = y + (size_t)ck * 2 * CH * TLEN * 64;

        meanln_kernel<<<CTOK, 256, 0, st>>>(x, ln_g, ln_b, snh, ck * 2);
        cudaStreamWaitEvent(st, eW, 0);

        // qkv: 2000 x 2304
        gemm_bf16<4,1><<<dim3(3*CH/128, 16), 256, GS_TOTAL, st>>>(
            snh_c, wqkvT, b_qkv, nullptr, qkv_c, CTOK, 3*CH, CH);
        attn_kernel<<<dim3(NWIN, HEADS, 2), 256, 0, st>>>(qkv_c, tau, att_c);

        // proj: 2000 x 768, split-K 2
        gemm_bf16<5,2><<<dim3(CH/128, 16, 2), 256, GS_TOTAL, st>>>(
            att_c, wprojT, nullptr, part_c, nullptr, CTOK, CH, CH);
        reduce_proj_kernel<<<(CTOK*CH/4 + 255)/256, 256, 0, st>>>(part_c, b_proj, y0_c, y0h_c);

        // mlp1 + gelu: 2000 x 3072
        gemm_bf16<1,1><<<dim3(MLPC/128, 16), 256, GS_TOTAL, st>>>(
            y0h_c, wmlp1T, b_mlp1, nullptr, mlp_c, CTOK, MLPC, CH);
        // mlp2: 2000 x 768, split-K 4
        gemm_bf16<5,4><<<dim3(CH/128, 16, 4), 256, GS_TOTAL, st>>>(
            mlp_c, wmlp2T, nullptr, part_c, nullptr, CTOK, CH, MLPC);
        reduce_mlp2_kernel<<<(CTOK*CH/4 + 255)/256, 256, 0, st>>>(part_c, b_mlp2, y0_c, o_c);

        final_kernel<<<(2*CH*TLEN*16 + 255)/256, 256, 0, st>>>(x_c, o_c, y_c);
    }

    // join
    cudaEventRecord(eA, sA);
    cudaEventRecord(eB, sB);
    cudaStreamWaitEvent(0, eA, 0);
    cudaStreamWaitEvent(0, eB, 0);
}